// round 9
// baseline (speedup 1.0000x reference)
#include <cuda_runtime.h>
#include <cstdint>

#define HF 128
#define WF 192
#define NA 9
#define HW (HF*WF)               // 24576
#define NTOT (HW*NA)             // 221184
#define TOPN 6000
#define POSTN 300
#define NB 94                    // ceil(6000/64)
#define TILE_WORDS (64*NB)       // 6016
#define CAND_MAX 16384
#define GB 128                   // blocks (<= SM count, 1 block/SM -> co-resident)
#define BT 1024                  // threads per block
#define GSZ (GB*BT)
#define NTRI (NB*(NB+1)/2)       // 4465 triangular tiles
#define TEAMS (GB*(BT/64))       // 2048 mask teams
#define MASK_ROUNDS ((NTRI + TEAMS - 1) / TEAMS)   // 3

__constant__ float c_anchors[NA][4] = {
    {-84.f,  -40.f,  99.f,  55.f},
    {-176.f, -88.f,  191.f, 103.f},
    {-360.f, -184.f, 375.f, 199.f},
    {-56.f,  -56.f,  71.f,  71.f},
    {-120.f, -120.f, 135.f, 135.f},
    {-248.f, -248.f, 263.f, 263.f},
    {-36.f,  -80.f,  51.f,  95.f},
    {-80.f,  -168.f, 95.f,  183.f},
    {-168.f, -344.f, 183.f, 359.f}
};

struct ZeroBlock {
    unsigned int hist[65536];
    unsigned long long sup[NB];
};
__device__ __align__(16) ZeroBlock g_z;

__device__ unsigned int g_srt[NTOT];
__device__ __align__(16) unsigned int g_sfx[65536];
__device__ unsigned int g_thresh;
__device__ unsigned int g_cand_count;
__device__ __align__(16) unsigned long long g_cand[CAND_MAX];
__device__ float4 g_top_boxes[TOPN];
__device__ unsigned long long g_mask[6016 * NB];

// ---- software grid barrier (all GB blocks co-resident by construction) ----
__device__ unsigned int g_bar_count;
__device__ unsigned int g_bar_gen;

__device__ __forceinline__ void grid_bar() {
    __threadfence();
    __syncthreads();
    if (threadIdx.x == 0) {
        unsigned int gen = atomicAdd(&g_bar_gen, 0u);
        if (atomicAdd(&g_bar_count, 1u) == GB - 1) {
            g_bar_count = 0;
            __threadfence();
            atomicAdd(&g_bar_gen, 1u);
        } else {
            while (atomicAdd(&g_bar_gen, 0u) == gen) { __nanosleep(128); }
        }
    }
    __syncthreads();
    __threadfence();
}

__device__ __forceinline__ void cp_async8(void* smem_dst, const void* gmem_src) {
    unsigned int d = (unsigned int)__cvta_generic_to_shared(smem_dst);
    asm volatile("cp.async.ca.shared.global [%0], [%1], 8;" :: "r"(d), "l"(gmem_src) : "memory");
}
__device__ __forceinline__ void cp_async_commit() {
    asm volatile("cp.async.commit_group;" ::: "memory");
}
__device__ __forceinline__ void cp_async_wait0() {
    asm volatile("cp.async.wait_group 0;" ::: "memory");
}

__device__ __forceinline__ float4 decode_from_deltas(int a, int k,
                                                     float dx, float dy, float dw, float dh,
                                                     float im0, float im1, float im2,
                                                     bool* valid) {
    int xs = k >> 7;          // meshgrid 'ij' quirk: shift row k -> (x=k/128, y=k%128)
    int ys = k & 127;
    float sx = 16.f * (float)xs;
    float sy = 16.f * (float)ys;
    float ax1 = c_anchors[a][0] + sx;
    float ay1 = c_anchors[a][1] + sy;
    float ax2 = c_anchors[a][2] + sx;
    float ay2 = c_anchors[a][3] + sy;

    float w = ax2 - ax1 + 1.f;
    float h = ay2 - ay1 + 1.f;
    float cx = ax1 + 0.5f * w;
    float cy = ay1 + 0.5f * h;

    float pcx = dx * w + cx;
    float pcy = dy * h + cy;
    float pw = expf(dw) * w;
    float ph = expf(dh) * h;

    float x1 = pcx - 0.5f * pw;
    float y1 = pcy - 0.5f * ph;
    float x2 = pcx + 0.5f * pw;
    float y2 = pcy + 0.5f * ph;

    x1 = fminf(fmaxf(x1, 0.f), im1 - 1.f);
    x2 = fminf(fmaxf(x2, 0.f), im1 - 1.f);
    y1 = fminf(fmaxf(y1, 0.f), im0 - 1.f);
    y2 = fminf(fmaxf(y2, 0.f), im0 - 1.f);

    float ms = 16.f * im2;
    *valid = (x2 - x1 + 1.f >= ms) && (y2 - y1 + 1.f >= ms);
    return make_float4(x1, y1, x2, y2);
}

__global__ void __launch_bounds__(BT, 1)
k_mega(const float* __restrict__ scores,
       const float* __restrict__ deltas,
       const float* __restrict__ im_info,
       float* __restrict__ out) {
    // ---- static shared (phase-disjoint) ----
    __shared__ unsigned int s_scan[256];
    __shared__ unsigned int s_S2[256];
    __shared__ int s_gsel;
    __shared__ unsigned int s_above;
    __shared__ float4 s_bb[16][64];
    __shared__ float s_ar[16][64];
    __shared__ unsigned long long s_remv[NB];
    __shared__ int s_klist[POSTN];
    extern __shared__ unsigned long long tiles[];   // 2 * TILE_WORDS (collect, block 0)

    const int tid = threadIdx.x;
    const int gtid = blockIdx.x * BT + tid;

    // ================= Phase 0: zero scratch =================
    {
        unsigned int* z = (unsigned int*)&g_z;
        const int nz = sizeof(ZeroBlock) / 4;
        for (int t = gtid; t < nz; t += GSZ) z[t] = 0u;
    }
    grid_bar();

    // ================= Phase 1: sortable scores + histogram =================
    for (int t = gtid; t < NTOT; t += GSZ) {
        int a = t / HW;
        int k = t - a * HW;
        float sc = scores[(NA + a) * HW + k];
        float dx = deltas[(4*a + 0) * HW + k];
        float dy = deltas[(4*a + 1) * HW + k];
        float dw = deltas[(4*a + 2) * HW + k];
        float dh = deltas[(4*a + 3) * HW + k];
        float im0 = im_info[0], im1 = im_info[1], im2 = im_info[2];
        bool valid;
        (void)decode_from_deltas(a, k, dx, dy, dw, dh, im0, im1, im2, &valid);
        unsigned int srt;
        if (valid) {
            unsigned int b = __float_as_uint(sc);
            srt = (b & 0x80000000u) ? ~b : (b | 0x80000000u);
        } else {
            srt = 0x007FFFFFu;   // flip(-inf)
        }
        g_srt[t] = srt;
        atomicAdd(&g_z.hist[srt >> 16], 1u);
    }
    grid_bar();

    // ================= Phase 2: suffix table + threshold (block 0) =================
    if (blockIdx.x == 0) {
        const uint4* h4 = (const uint4*)g_z.hist;
        if (tid < 256) {
            unsigned int sum = 0;
#pragma unroll 8
            for (int b = 0; b < 64; b++) {
                uint4 v = h4[tid * 64 + b];
                sum += v.x + v.y + v.z + v.w;
            }
            s_scan[tid] = sum;
        }
        __syncthreads();
        for (int off = 1; off < 256; off <<= 1) {
            unsigned int v = 0;
            if (tid < 256) v = (tid + off < 256) ? s_scan[tid + off] : 0u;
            __syncthreads();
            if (tid < 256) s_scan[tid] += v;
            __syncthreads();
        }
        if (tid < 256) s_S2[tid] = s_scan[tid];
        __syncthreads();

        if (tid < 256) {
            unsigned int run = (tid == 255) ? 0u : s_S2[tid + 1];
            uint4* s4 = (uint4*)g_sfx;
#pragma unroll 4
            for (int q = 63; q >= 0; q--) {
                int idx4 = tid * 64 + q;
                uint4 h = h4[idx4];
                uint4 o;
                o.w = run; run += h.w;
                o.z = run; run += h.z;
                o.y = run; run += h.y;
                o.x = run; run += h.x;
                s4[idx4] = o;
            }
            unsigned int nxt = (tid == 255) ? 0u : s_S2[tid + 1];
            if (s_S2[tid] >= TOPN && nxt < TOPN) { s_gsel = tid; s_above = nxt; }
        }
        __syncthreads();
        int g = s_gsel;
        unsigned int above = s_above;
        unsigned int fv = 0;
        if (tid < 256) fv = g_z.hist[g * 256 + tid];
        __syncthreads();
        if (tid < 256) s_scan[tid] = fv;
        __syncthreads();
        for (int off = 1; off < 256; off <<= 1) {
            unsigned int v = 0;
            if (tid < 256) v = (tid + off < 256) ? s_scan[tid + off] : 0u;
            __syncthreads();
            if (tid < 256) s_scan[tid] += v;
            __syncthreads();
        }
        if (tid < 256) {
            unsigned int nxt2 = (tid == 255) ? 0u : s_scan[tid + 1];
            if (above + s_scan[tid] >= TOPN && above + nxt2 < TOPN) {
                g_thresh = (unsigned int)(g * 256 + tid);
                g_cand_count = above + s_scan[tid];
            }
        }
    }
    grid_bar();

    // ================= Phase 3: compact into bucket-ordered slots =================
    {
        unsigned int thr = g_thresh;
        for (int t = gtid; t < NTOT; t += GSZ) {
            unsigned int srt = g_srt[t];
            unsigned int b = srt >> 16;
            if (b >= thr) {
                int a = t / HW;
                int k = t - a * HW;
                int i_ref = k * NA + a;
                unsigned long long key =
                    ((unsigned long long)srt << 32) | (0xFFFFFFFFu - (unsigned int)i_ref);
                unsigned int end = g_sfx[b - 1];
                unsigned int old = atomicSub(&g_z.hist[b], 1u);
                unsigned int slot = end - old;
                if (slot < CAND_MAX) g_cand[slot] = key;
            }
        }
    }
    grid_bar();

    // ================= Phase 4: in-bucket rank + decode + scatter =================
    {
        unsigned int C = g_cand_count;
        if (C > CAND_MAX) C = CAND_MAX;
        if (gtid < (int)C) {
            unsigned long long mykey = g_cand[gtid];
            unsigned int b = (unsigned int)(mykey >> 48);
            unsigned int idx = 0xFFFFFFFFu - (unsigned int)(mykey & 0xFFFFFFFFull);
            int a = idx % NA;
            int k = idx / NA;
            float dx = __ldg(&deltas[(4*a + 0) * HW + k]);
            float dy = __ldg(&deltas[(4*a + 1) * HW + k]);
            float dw = __ldg(&deltas[(4*a + 2) * HW + k]);
            float dh = __ldg(&deltas[(4*a + 3) * HW + k]);
            float im0 = __ldg(&im_info[0]), im1 = __ldg(&im_info[1]), im2 = __ldg(&im_info[2]);
            unsigned int base = g_sfx[b];
            unsigned int end = g_sfx[b - 1];
            if (end > C) end = C;
            unsigned int rank = base;
            for (unsigned int j = base; j < end; j++)
                rank += (g_cand[j] > mykey) ? 1u : 0u;
            if (rank < TOPN) {
                bool valid;
                float4 box = decode_from_deltas(a, k, dx, dy, dw, dh, im0, im1, im2, &valid);
                g_top_boxes[rank] = box;
                bool vkey = ((unsigned int)(mykey >> 32)) > 0x007FFFFFu;
                if (!vkey) atomicOr(&g_z.sup[rank >> 6], 1ull << (rank & 63));
            }
        }
    }
    grid_bar();

    // ================= Phase 5: NMS bitmask (teams of 64) =================
    {
        int team = tid >> 6;
        int t64 = tid & 63;
        for (int rnd = 0; rnd < MASK_ROUNDS; rnd++) {
            int lin = rnd * TEAMS + blockIdx.x * (BT / 64) + team;
            bool active = (lin < NTRI);
            int bi = 0, bj = 0;
            if (active) {
                float f = 2.f * NB + 1.f;
                bi = (int)((f - sqrtf(f * f - 8.f * (float)lin)) * 0.5f);
                while (bi > 0 && (bi * NB - (bi * (bi - 1)) / 2) > lin) bi--;
                while (((bi + 1) * NB - ((bi + 1) * bi) / 2) <= lin) bi++;
                bj = bi + (lin - (bi * NB - (bi * (bi - 1)) / 2));
                int jg0 = bj * 64 + t64;
                if (jg0 < TOPN) {
                    float4 b = g_top_boxes[jg0];
                    s_bb[team][t64] = b;
                    s_ar[team][t64] = (b.z - b.x) * (b.w - b.y);
                } else {
                    s_bb[team][t64] = make_float4(0.f, 0.f, 0.f, 0.f);
                    s_ar[team][t64] = 0.f;
                }
            }
            __syncthreads();
            if (active) {
                int i = bi * 64 + t64;
                if (i < TOPN) {
                    float4 bib = g_top_boxes[i];
                    float area_i = (bib.z - bib.x) * (bib.w - bib.y);
                    unsigned long long m = 0ull;
#pragma unroll 4
                    for (int jj = 0; jj < 64; jj++) {
                        int jg = bj * 64 + jj;
                        float4 bjb = s_bb[team][jj];
                        float ix1 = fmaxf(bib.x, bjb.x);
                        float iy1 = fmaxf(bib.y, bjb.y);
                        float ix2 = fminf(bib.z, bjb.z);
                        float iy2 = fminf(bib.w, bjb.w);
                        float inter = fmaxf(ix2 - ix1, 0.f) * fmaxf(iy2 - iy1, 0.f);
                        float denom = fmaxf(area_i + s_ar[team][jj] - inter, 1e-9f);
                        float iou = inter / denom;
                        if (iou > 0.7f && jg > i && jg < TOPN) m |= (1ull << jj);
                    }
                    g_mask[(size_t)i * NB + bj] = m;
                }
            }
            __syncthreads();
        }
    }
    grid_bar();

    // ================= Phase 6: greedy collect (block 0 only) =================
    if (blockIdx.x != 0) return;
    {
        for (int t = tid; t < POSTN * 5; t += BT) out[t] = 0.f;  // d_out is poisoned
        for (int t = tid; t < NB; t += BT) {
            unsigned long long m = g_z.sup[t];
            if (t == NB - 1) m |= 0xFFFF000000000000ull;   // bits >= 6000
            s_remv[t] = m;
        }
        __syncthreads();

        // prefetch tile 0 (alive rows only)
        {
            unsigned long long rv = s_remv[0];
            for (int t = tid; t < 64 * NB; t += BT) {
                int r = t / NB, w = t - r * NB;
                if (!((rv >> r) & 1ull))
                    cp_async8(&tiles[t], &g_mask[(size_t)r * NB + w]);
            }
            cp_async_commit();
        }
        cp_async_wait0();
        __syncthreads();

        int kept = 0;
        for (int ib = 0; ib < NB; ib++) {
            unsigned long long* tile = tiles + (size_t)(ib & 1) * TILE_WORDS;
            if (ib + 1 < NB) {
                int nb2 = ib + 1;
                int wcnt2 = NB - nb2;
                int rows2 = TOPN - nb2 * 64; if (rows2 > 64) rows2 = 64;
                unsigned long long rv = s_remv[nb2];
                unsigned long long* dst = tiles + (size_t)(nb2 & 1) * TILE_WORDS;
                for (int t = tid; t < rows2 * wcnt2; t += BT) {
                    int r = t / wcnt2, w = t - r * wcnt2;
                    if (!((rv >> r) & 1ull))
                        cp_async8(&dst[t], &g_mask[(size_t)(nb2 * 64 + r) * NB + nb2 + w]);
                }
            }
            cp_async_commit();

            int wcnt = NB - ib;
            unsigned long long rcur = s_remv[ib];
            unsigned long long acc = 0ull;
            int w = tid;
            while (true) {
                unsigned long long avail = ~rcur;
                if (avail == 0ull) break;
                int bit = __ffsll((long long)avail) - 1;
                if (tid == 0) s_klist[kept] = ib * 64 + bit;
                kept++;
                rcur |= tile[bit * wcnt] | (1ull << bit);
                if (w > 0 && w < wcnt) acc |= tile[bit * wcnt + w];
                if (kept >= POSTN) break;
            }
            if (w > 0 && w < wcnt) s_remv[ib + w] |= acc;
            if (kept >= POSTN) break;
            cp_async_wait0();
            __syncthreads();
        }

        cp_async_wait0();
        __syncthreads();
        for (int t = tid; t < kept; t += BT) {
            int idx = s_klist[t];
            float4 b = g_top_boxes[idx];
            float* row = out + t * 5;
            row[0] = 0.f; row[1] = b.x; row[2] = b.y; row[3] = b.z; row[4] = b.w;
        }
    }
}

extern "C" void kernel_launch(void* const* d_in, const int* in_sizes, int n_in,
                              void* d_out, int out_size) {
    const float* scores  = (const float*)d_in[0];
    const float* deltas  = (const float*)d_in[1];
    const float* im_info = (const float*)d_in[2];
    float* out = (float*)d_out;

    size_t dyn = (size_t)2 * TILE_WORDS * sizeof(unsigned long long);  // 96256 B
    cudaFuncSetAttribute(k_mega, cudaFuncAttributeMaxDynamicSharedMemorySize, (int)dyn);
    k_mega<<<GB, BT, dyn>>>(scores, deltas, im_info, out);
}

// round 10
// speedup vs baseline: 1.2981x; 1.2981x over previous
#include <cuda_runtime.h>
#include <cstdint>

#define HF 128
#define WF 192
#define NA 9
#define HW (HF*WF)               // 24576
#define NTOT (HW*NA)             // 221184
#define TOPN 6000
#define POSTN 300
#define NB 94                    // ceil(6000/64)
#define TILE_WORDS (64*NB)       // 6016
#define CAND_MAX 16384
#define CTH 512                  // collect threads

__constant__ float c_anchors[NA][4] = {
    {-84.f,  -40.f,  99.f,  55.f},
    {-176.f, -88.f,  191.f, 103.f},
    {-360.f, -184.f, 375.f, 199.f},
    {-56.f,  -56.f,  71.f,  71.f},
    {-120.f, -120.f, 135.f, 135.f},
    {-248.f, -248.f, 263.f, 263.f},
    {-36.f,  -80.f,  51.f,  95.f},
    {-80.f,  -168.f, 95.f,  183.f},
    {-168.f, -344.f, 183.f, 359.f}
};

// single zeroed region (one memset node)
struct ZeroBlock {
    unsigned int hist[65536];
    unsigned long long sup[NB];
};
__device__ __align__(16) ZeroBlock g_z;

__device__ unsigned int g_srt[NTOT];                 // 32-bit sortable score
__device__ float4 g_boxes[NTOT];                     // t = a*HW + k
__device__ __align__(16) unsigned int g_sfx[65536];  // sfx[b] = #keys in buckets > b
__device__ unsigned int g_thresh;
__device__ unsigned int g_cand_count;
__device__ __align__(16) unsigned long long g_cand[CAND_MAX];
__device__ float4 g_top_boxes[TOPN];
__device__ unsigned long long g_mask[6016 * NB];

__device__ __forceinline__ void cp_async8(void* smem_dst, const void* gmem_src) {
    unsigned int d = (unsigned int)__cvta_generic_to_shared(smem_dst);
    asm volatile("cp.async.ca.shared.global [%0], [%1], 8;" :: "r"(d), "l"(gmem_src) : "memory");
}
__device__ __forceinline__ void cp_async_commit() {
    asm volatile("cp.async.commit_group;" ::: "memory");
}
__device__ __forceinline__ void cp_async_wait0() {
    asm volatile("cp.async.wait_group 0;" ::: "memory");
}

// ---------------- K1: decode + boxes + sortable score + histogram ----------------
__global__ void k_score_box(const float* __restrict__ scores,
                            const float* __restrict__ deltas,
                            const float* __restrict__ im_info) {
    int t = blockIdx.x * blockDim.x + threadIdx.x;
    if (t >= NTOT) return;
    int a = t / HW;
    int k = t - a * HW;
    int xs = k >> 7;          // meshgrid 'ij' quirk: shift row k -> (x=k/128, y=k%128)
    int ys = k & 127;

    float sc = scores[(NA + a) * HW + k];
    float dx = deltas[(4*a + 0) * HW + k];
    float dy = deltas[(4*a + 1) * HW + k];
    float dw = deltas[(4*a + 2) * HW + k];
    float dh = deltas[(4*a + 3) * HW + k];

    float sx = 16.f * (float)xs;
    float sy = 16.f * (float)ys;
    float ax1 = c_anchors[a][0] + sx;
    float ay1 = c_anchors[a][1] + sy;
    float ax2 = c_anchors[a][2] + sx;
    float ay2 = c_anchors[a][3] + sy;

    float w = ax2 - ax1 + 1.f;
    float h = ay2 - ay1 + 1.f;
    float cx = ax1 + 0.5f * w;
    float cy = ay1 + 0.5f * h;

    float pcx = dx * w + cx;
    float pcy = dy * h + cy;
    float pw = expf(dw) * w;
    float ph = expf(dh) * h;

    float x1 = pcx - 0.5f * pw;
    float y1 = pcy - 0.5f * ph;
    float x2 = pcx + 0.5f * pw;
    float y2 = pcy + 0.5f * ph;

    float im0 = im_info[0], im1 = im_info[1], im2 = im_info[2];
    x1 = fminf(fmaxf(x1, 0.f), im1 - 1.f);
    x2 = fminf(fmaxf(x2, 0.f), im1 - 1.f);
    y1 = fminf(fmaxf(y1, 0.f), im0 - 1.f);
    y2 = fminf(fmaxf(y2, 0.f), im0 - 1.f);

    float ms = 16.f * im2;
    bool valid = (x2 - x1 + 1.f >= ms) && (y2 - y1 + 1.f >= ms);

    unsigned int srt;
    if (valid) {
        unsigned int b = __float_as_uint(sc);
        srt = (b & 0x80000000u) ? ~b : (b | 0x80000000u);
    } else {
        srt = 0x007FFFFFu;   // flip(-inf)
    }
    g_srt[t] = srt;
    g_boxes[t] = make_float4(x1, y1, x2, y2);
    atomicAdd(&g_z.hist[srt >> 16], 1u);
}

// ---------------- K2: suffix table + threshold + candidate count ----------------
__global__ void k_thresh() {
    __shared__ unsigned int s[256];
    __shared__ unsigned int S2[256];
    __shared__ int gsel;
    __shared__ unsigned int above_s;
    int t = threadIdx.x;
    unsigned int sum = 0;
    const uint4* h4 = (const uint4*)g_z.hist;
#pragma unroll 8
    for (int b = 0; b < 64; b++) {
        uint4 v = h4[t * 64 + b];
        sum += v.x + v.y + v.z + v.w;
    }
    s[t] = sum;
    __syncthreads();
    for (int off = 1; off < 256; off <<= 1) {
        unsigned int v = (t + off < 256) ? s[t + off] : 0u;
        __syncthreads();
        s[t] += v;
        __syncthreads();
    }
    S2[t] = s[t];
    __syncthreads();

    // full per-bucket suffix table
    {
        unsigned int run = (t == 255) ? 0u : S2[t + 1];
        uint4* s4 = (uint4*)g_sfx;
#pragma unroll 4
        for (int q = 63; q >= 0; q--) {
            int idx4 = t * 64 + q;
            uint4 h = h4[idx4];
            uint4 o;
            o.w = run; run += h.w;
            o.z = run; run += h.z;
            o.y = run; run += h.y;
            o.x = run; run += h.x;
            s4[idx4] = o;
        }
    }

    unsigned int nxt = (t == 255) ? 0u : S2[t + 1];
    if (S2[t] >= TOPN && nxt < TOPN) { gsel = t; above_s = nxt; }
    __syncthreads();
    int g = gsel;
    unsigned int above = above_s;
    unsigned int fv = g_z.hist[g * 256 + t];
    __syncthreads();
    s[t] = fv;
    __syncthreads();
    for (int off = 1; off < 256; off <<= 1) {
        unsigned int v = (t + off < 256) ? s[t + off] : 0u;
        __syncthreads();
        s[t] += v;
        __syncthreads();
    }
    unsigned int nxt2 = (t == 255) ? 0u : s[t + 1];
    if (above + s[t] >= TOPN && above + nxt2 < TOPN) {
        g_thresh = (unsigned int)(g * 256 + t);
        g_cand_count = above + s[t];
    }
}

// ---------------- K3: compact candidates into bucket-ordered slots ----------------
__global__ void k_compact() {
    int t = blockIdx.x * blockDim.x + threadIdx.x;
    if (t >= NTOT) return;
    unsigned int srt = g_srt[t];
    unsigned int b = srt >> 16;
    if (b >= g_thresh) {
        int a = t / HW;
        int k = t - a * HW;
        int i_ref = k * NA + a;   // reference flatten order (tiebreak)
        unsigned long long key =
            ((unsigned long long)srt << 32) | (0xFFFFFFFFu - (unsigned int)i_ref);
        unsigned int end = g_sfx[b - 1];                 // b >= thresh >= 1
        unsigned int old = atomicSub(&g_z.hist[b], 1u);  // counts down
        unsigned int slot = end - old;                   // bucket base .. end-1
        if (slot < CAND_MAX) g_cand[slot] = key;
    }
}

// ---------------- K4: in-bucket exact rank + gather + scatter ----------------
__global__ void k_ranksc() {
    unsigned int C = g_cand_count;
    if (C > CAND_MAX) C = CAND_MAX;
    int i = blockIdx.x * blockDim.x + threadIdx.x;
    if (i >= (int)C) return;
    unsigned long long mykey = g_cand[i];
    unsigned int b = (unsigned int)(mykey >> 48);

    // hoist independent loads ahead of the rank loop
    unsigned int idx = 0xFFFFFFFFu - (unsigned int)(mykey & 0xFFFFFFFFull);
    int a = idx % NA;
    int k = idx / NA;
    float4 box = g_boxes[a * HW + k];
    unsigned int base = g_sfx[b];
    unsigned int end = g_sfx[b - 1];
    if (end > C) end = C;

    unsigned int rank = base;
    for (unsigned int j = base; j < end; j++)
        rank += (g_cand[j] > mykey) ? 1u : 0u;

    if (rank < TOPN) {
        g_top_boxes[rank] = box;
        bool vkey = ((unsigned int)(mykey >> 32)) > 0x007FFFFFu;
        if (!vkey) atomicOr(&g_z.sup[rank >> 6], 1ull << (rank & 63));
    }
}

// ---------------- K5: NMS suppression bitmask (upper triangle only) ----------------
__global__ void k_mask() {
    int bi = blockIdx.y, bj = blockIdx.x;
    if (bj < bi) return;
    int t = threadIdx.x;
    int i = bi * 64 + t;
    __shared__ float4 bb[64];
    __shared__ float ar[64];
    int jg0 = bj * 64 + t;
    if (jg0 < TOPN) {
        float4 b = g_top_boxes[jg0];
        bb[t] = b;
        ar[t] = (b.z - b.x) * (b.w - b.y);
    } else {
        bb[t] = make_float4(0.f, 0.f, 0.f, 0.f);
        ar[t] = 0.f;
    }
    __syncthreads();
    if (i >= TOPN) return;
    float4 bi_box = g_top_boxes[i];
    float area_i = (bi_box.z - bi_box.x) * (bi_box.w - bi_box.y);
    unsigned long long m = 0ull;
#pragma unroll 4
    for (int jj = 0; jj < 64; jj++) {
        int jg = bj * 64 + jj;
        float4 bj_box = bb[jj];
        float ix1 = fmaxf(bi_box.x, bj_box.x);
        float iy1 = fmaxf(bi_box.y, bj_box.y);
        float ix2 = fminf(bi_box.z, bj_box.z);
        float iy2 = fminf(bi_box.w, bj_box.w);
        float inter = fmaxf(ix2 - ix1, 0.f) * fmaxf(iy2 - iy1, 0.f);
        float denom = fmaxf(area_i + ar[jj] - inter, 1e-9f);
        float iou = inter / denom;
        if (iou > 0.7f && jg > i && jg < TOPN) m |= (1ull << jj);
    }
    g_mask[(size_t)i * NB + bj] = m;
}

// ---------------- K6: greedy collect, deferred-OR, cp.async double buffer ----
// Control flow uniform across block (branch data identical per thread).
__global__ void __launch_bounds__(CTH) k_collect(float* __restrict__ out) {
    __shared__ unsigned long long remv[NB];
    __shared__ int klist[POSTN];
    extern __shared__ unsigned long long tiles[];  // 2 * TILE_WORDS
    int tid = threadIdx.x;

    for (int t = tid; t < POSTN * 5; t += CTH) out[t] = 0.f;  // d_out is poisoned
    for (int t = tid; t < NB; t += CTH) {
        unsigned long long m = g_z.sup[t];
        if (t == NB - 1) m |= 0xFFFF000000000000ull;   // bits 48..63 (>= 6000)
        remv[t] = m;
    }

    // prefetch tile 0 (dense — measured best in R5)
    {
        for (int t = tid; t < 64 * NB; t += CTH) {
            int r = t / NB, w = t - r * NB;
            cp_async8(&tiles[t], &g_mask[(size_t)r * NB + w]);
        }
        cp_async_commit();
    }
    cp_async_wait0();
    __syncthreads();

    int kept = 0;
    for (int ib = 0; ib < NB; ib++) {
        unsigned long long* tile = tiles + (size_t)(ib & 1) * TILE_WORDS;
        if (ib + 1 < NB) {
            int nb2 = ib + 1;
            int wcnt2 = NB - nb2;
            int rows2 = TOPN - nb2 * 64; if (rows2 > 64) rows2 = 64;
            unsigned long long* dst = tiles + (size_t)(nb2 & 1) * TILE_WORDS;
            for (int t = tid; t < rows2 * wcnt2; t += CTH) {
                int r = t / wcnt2, w = t - r * wcnt2;
                cp_async8(&dst[t], &g_mask[(size_t)(nb2 * 64 + r) * NB + nb2 + w]);
            }
        }
        cp_async_commit();

        int wcnt = NB - ib;
        unsigned long long rcur = remv[ib];
        unsigned long long acc = 0ull;
        int w = tid;                       // this thread owns word ib+w (w<wcnt)
        while (true) {
            unsigned long long avail = ~rcur;
            if (avail == 0ull) break;
            int bit = __ffsll((long long)avail) - 1;
            if (tid == 0) klist[kept] = ib * 64 + bit;
            kept++;
            rcur |= tile[bit * wcnt] | (1ull << bit);      // self word + mark done
            if (w > 0 && w < wcnt) acc |= tile[bit * wcnt + w];
            if (kept >= POSTN) break;
        }
        if (w > 0 && w < wcnt) remv[ib + w] |= acc;
        if (kept >= POSTN) break;
        cp_async_wait0();
        __syncthreads();
    }

    cp_async_wait0();
    __syncthreads();
    for (int t = tid; t < kept; t += CTH) {
        int idx = klist[t];
        float4 b = g_top_boxes[idx];
        float* row = out + t * 5;
        row[0] = 0.f; row[1] = b.x; row[2] = b.y; row[3] = b.z; row[4] = b.w;
    }
}

extern "C" void kernel_launch(void* const* d_in, const int* in_sizes, int n_in,
                              void* d_out, int out_size) {
    const float* scores  = (const float*)d_in[0];
    const float* deltas  = (const float*)d_in[1];
    const float* im_info = (const float*)d_in[2];
    float* out = (float*)d_out;

    void* p;
    cudaGetSymbolAddress(&p, g_z);
    cudaMemsetAsync(p, 0, sizeof(ZeroBlock));

    k_score_box<<<(NTOT + 255) / 256, 256>>>(scores, deltas, im_info);
    k_thresh<<<1, 256>>>();
    k_compact<<<(NTOT + 255) / 256, 256>>>();
    k_ranksc<<<CAND_MAX / 128, 128>>>();

    dim3 gm(NB, NB);
    k_mask<<<gm, 64>>>();

    size_t csh = (size_t)2 * TILE_WORDS * sizeof(unsigned long long);
    cudaFuncSetAttribute(k_collect, cudaFuncAttributeMaxDynamicSharedMemorySize, (int)csh);
    k_collect<<<1, CTH, csh>>>(out);
}

// round 11
// speedup vs baseline: 1.3084x; 1.0080x over previous
#include <cuda_runtime.h>
#include <cstdint>

#define HF 128
#define WF 192
#define NA 9
#define HW (HF*WF)               // 24576
#define NTOT (HW*NA)             // 221184
#define TOPN 6000
#define POSTN 300
#define NB 94                    // ceil(6000/64)
#define TILE_WORDS (64*NB)       // 6016
#define CAND_MAX 16384
#define CTH 512                  // collect threads

__constant__ float c_anchors[NA][4] = {
    {-84.f,  -40.f,  99.f,  55.f},
    {-176.f, -88.f,  191.f, 103.f},
    {-360.f, -184.f, 375.f, 199.f},
    {-56.f,  -56.f,  71.f,  71.f},
    {-120.f, -120.f, 135.f, 135.f},
    {-248.f, -248.f, 263.f, 263.f},
    {-36.f,  -80.f,  51.f,  95.f},
    {-80.f,  -168.f, 95.f,  183.f},
    {-168.f, -344.f, 183.f, 359.f}
};

// single zeroed region (one memset node)
struct ZeroBlock {
    unsigned int hist[65536];
    unsigned long long sup[NB];
};
__device__ __align__(16) ZeroBlock g_z;

__device__ unsigned int g_srt[NTOT];                 // 32-bit sortable score
__device__ float4 g_boxes[NTOT];                     // t = a*HW + k
__device__ __align__(16) unsigned int g_sfx[65536];  // sfx[b] = #keys in buckets > b
__device__ unsigned int g_thresh;
__device__ unsigned int g_cand_count;
__device__ __align__(16) unsigned long long g_cand[CAND_MAX];
__device__ float4 g_top_boxes[TOPN];
__device__ __align__(16) unsigned long long g_mask[6016 * NB];

__device__ __forceinline__ void cp_async16(void* smem_dst, const void* gmem_src) {
    unsigned int d = (unsigned int)__cvta_generic_to_shared(smem_dst);
    asm volatile("cp.async.cg.shared.global [%0], [%1], 16;" :: "r"(d), "l"(gmem_src) : "memory");
}
__device__ __forceinline__ void cp_async_commit() {
    asm volatile("cp.async.commit_group;" ::: "memory");
}
__device__ __forceinline__ void cp_async_wait0() {
    asm volatile("cp.async.wait_group 0;" ::: "memory");
}

// ---------------- K1: decode + boxes + sortable score + histogram ----------------
__global__ void k_score_box(const float* __restrict__ scores,
                            const float* __restrict__ deltas,
                            const float* __restrict__ im_info) {
    int t = blockIdx.x * blockDim.x + threadIdx.x;
    if (t >= NTOT) return;
    int a = t / HW;
    int k = t - a * HW;
    int xs = k >> 7;          // meshgrid 'ij' quirk: shift row k -> (x=k/128, y=k%128)
    int ys = k & 127;

    float sc = scores[(NA + a) * HW + k];
    float dx = deltas[(4*a + 0) * HW + k];
    float dy = deltas[(4*a + 1) * HW + k];
    float dw = deltas[(4*a + 2) * HW + k];
    float dh = deltas[(4*a + 3) * HW + k];

    float sx = 16.f * (float)xs;
    float sy = 16.f * (float)ys;
    float ax1 = c_anchors[a][0] + sx;
    float ay1 = c_anchors[a][1] + sy;
    float ax2 = c_anchors[a][2] + sx;
    float ay2 = c_anchors[a][3] + sy;

    float w = ax2 - ax1 + 1.f;
    float h = ay2 - ay1 + 1.f;
    float cx = ax1 + 0.5f * w;
    float cy = ay1 + 0.5f * h;

    float pcx = dx * w + cx;
    float pcy = dy * h + cy;
    float pw = expf(dw) * w;
    float ph = expf(dh) * h;

    float x1 = pcx - 0.5f * pw;
    float y1 = pcy - 0.5f * ph;
    float x2 = pcx + 0.5f * pw;
    float y2 = pcy + 0.5f * ph;

    float im0 = im_info[0], im1 = im_info[1], im2 = im_info[2];
    x1 = fminf(fmaxf(x1, 0.f), im1 - 1.f);
    x2 = fminf(fmaxf(x2, 0.f), im1 - 1.f);
    y1 = fminf(fmaxf(y1, 0.f), im0 - 1.f);
    y2 = fminf(fmaxf(y2, 0.f), im0 - 1.f);

    float ms = 16.f * im2;
    bool valid = (x2 - x1 + 1.f >= ms) && (y2 - y1 + 1.f >= ms);

    unsigned int srt;
    if (valid) {
        unsigned int b = __float_as_uint(sc);
        srt = (b & 0x80000000u) ? ~b : (b | 0x80000000u);
    } else {
        srt = 0x007FFFFFu;   // flip(-inf)
    }
    g_srt[t] = srt;
    g_boxes[t] = make_float4(x1, y1, x2, y2);
    atomicAdd(&g_z.hist[srt >> 16], 1u);
}

// ---------------- K2: suffix table + threshold + candidate count ----------------
__global__ void k_thresh() {
    __shared__ unsigned int s[256];
    __shared__ unsigned int S2[256];
    __shared__ int gsel;
    __shared__ unsigned int above_s;
    int t = threadIdx.x;
    unsigned int sum = 0;
    const uint4* h4 = (const uint4*)g_z.hist;
#pragma unroll 8
    for (int b = 0; b < 64; b++) {
        uint4 v = h4[t * 64 + b];
        sum += v.x + v.y + v.z + v.w;
    }
    s[t] = sum;
    __syncthreads();
    for (int off = 1; off < 256; off <<= 1) {
        unsigned int v = (t + off < 256) ? s[t + off] : 0u;
        __syncthreads();
        s[t] += v;
        __syncthreads();
    }
    S2[t] = s[t];
    __syncthreads();

    // full per-bucket suffix table
    {
        unsigned int run = (t == 255) ? 0u : S2[t + 1];
        uint4* s4 = (uint4*)g_sfx;
#pragma unroll 4
        for (int q = 63; q >= 0; q--) {
            int idx4 = t * 64 + q;
            uint4 h = h4[idx4];
            uint4 o;
            o.w = run; run += h.w;
            o.z = run; run += h.z;
            o.y = run; run += h.y;
            o.x = run; run += h.x;
            s4[idx4] = o;
        }
    }

    unsigned int nxt = (t == 255) ? 0u : S2[t + 1];
    if (S2[t] >= TOPN && nxt < TOPN) { gsel = t; above_s = nxt; }
    __syncthreads();
    int g = gsel;
    unsigned int above = above_s;
    unsigned int fv = g_z.hist[g * 256 + t];
    __syncthreads();
    s[t] = fv;
    __syncthreads();
    for (int off = 1; off < 256; off <<= 1) {
        unsigned int v = (t + off < 256) ? s[t + off] : 0u;
        __syncthreads();
        s[t] += v;
        __syncthreads();
    }
    unsigned int nxt2 = (t == 255) ? 0u : s[t + 1];
    if (above + s[t] >= TOPN && above + nxt2 < TOPN) {
        g_thresh = (unsigned int)(g * 256 + t);
        g_cand_count = above + s[t];
    }
}

// ---------------- K3: compact candidates into bucket-ordered slots ----------------
__global__ void k_compact() {
    int t = blockIdx.x * blockDim.x + threadIdx.x;
    if (t >= NTOT) return;
    unsigned int srt = g_srt[t];
    unsigned int b = srt >> 16;
    if (b >= g_thresh) {
        int a = t / HW;
        int k = t - a * HW;
        int i_ref = k * NA + a;   // reference flatten order (tiebreak)
        unsigned long long key =
            ((unsigned long long)srt << 32) | (0xFFFFFFFFu - (unsigned int)i_ref);
        unsigned int end = g_sfx[b - 1];                 // b >= thresh >= 1
        unsigned int old = atomicSub(&g_z.hist[b], 1u);  // counts down
        unsigned int slot = end - old;                   // bucket base .. end-1
        if (slot < CAND_MAX) g_cand[slot] = key;
    }
}

// ---------------- K4: in-bucket exact rank + gather + scatter ----------------
__global__ void k_ranksc() {
    unsigned int C = g_cand_count;
    if (C > CAND_MAX) C = CAND_MAX;
    int i = blockIdx.x * blockDim.x + threadIdx.x;
    if (i >= (int)C) return;
    unsigned long long mykey = g_cand[i];
    unsigned int b = (unsigned int)(mykey >> 48);

    unsigned int idx = 0xFFFFFFFFu - (unsigned int)(mykey & 0xFFFFFFFFull);
    int a = idx % NA;
    int k = idx / NA;
    float4 box = g_boxes[a * HW + k];
    unsigned int base = g_sfx[b];
    unsigned int end = g_sfx[b - 1];
    if (end > C) end = C;

    unsigned int rank = base;
    for (unsigned int j = base; j < end; j++)
        rank += (g_cand[j] > mykey) ? 1u : 0u;

    if (rank < TOPN) {
        g_top_boxes[rank] = box;
        bool vkey = ((unsigned int)(mykey >> 32)) > 0x007FFFFFu;
        if (!vkey) atomicOr(&g_z.sup[rank >> 6], 1ull << (rank & 63));
    }
}

// ---------------- K5: NMS suppression bitmask (upper triangle only) ----------------
__global__ void k_mask() {
    int bi = blockIdx.y, bj = blockIdx.x;
    if (bj < bi) return;
    int t = threadIdx.x;
    int i = bi * 64 + t;
    __shared__ float4 bb[64];
    __shared__ float ar[64];
    int jg0 = bj * 64 + t;
    if (jg0 < TOPN) {
        float4 b = g_top_boxes[jg0];
        bb[t] = b;
        ar[t] = (b.z - b.x) * (b.w - b.y);
    } else {
        bb[t] = make_float4(0.f, 0.f, 0.f, 0.f);
        ar[t] = 0.f;
    }
    __syncthreads();
    if (i >= TOPN) return;
    float4 bi_box = g_top_boxes[i];
    float area_i = (bi_box.z - bi_box.x) * (bi_box.w - bi_box.y);
    unsigned long long m = 0ull;
#pragma unroll 4
    for (int jj = 0; jj < 64; jj++) {
        int jg = bj * 64 + jj;
        float4 bj_box = bb[jj];
        float ix1 = fmaxf(bi_box.x, bj_box.x);
        float iy1 = fmaxf(bi_box.y, bj_box.y);
        float ix2 = fminf(bi_box.z, bj_box.z);
        float iy2 = fminf(bi_box.w, bj_box.w);
        float inter = fmaxf(ix2 - ix1, 0.f) * fmaxf(iy2 - iy1, 0.f);
        float denom = fmaxf(area_i + ar[jj] - inter, 1e-9f);
        float iou = inter / denom;
        if (iou > 0.7f && jg > i && jg < TOPN) m |= (1ull << jj);
    }
    g_mask[(size_t)i * NB + bj] = m;
}

// ---------------- K6: greedy collect, 16B predicated cp.async ----------
// Control flow uniform across block (branch data identical per thread).
// Tiles are staged from even column ibe = ib & ~1 so both gmem and smem
// sides of every 16-byte cp.async are 16B-aligned (row stride 94*8 = 47*16).
__global__ void __launch_bounds__(CTH) k_collect(float* __restrict__ out) {
    __shared__ unsigned long long remv[NB];
    __shared__ int klist[POSTN];
    extern __shared__ unsigned long long tiles[];  // 2 * TILE_WORDS
    int tid = threadIdx.x;

    for (int t = tid; t < POSTN * 5; t += CTH) out[t] = 0.f;  // d_out is poisoned
    for (int t = tid; t < NB; t += CTH) {
        unsigned long long m = g_z.sup[t];
        if (t == NB - 1) m |= 0xFFFF000000000000ull;   // bits 48..63 (>= 6000)
        remv[t] = m;
    }
    __syncthreads();

    // prefetch tile 0 (ibe=0, wfull=NB even): alive rows only, 16B chunks
    {
        unsigned long long rv = remv[0];
        const int half = NB / 2;
        for (int t = tid; t < 64 * half; t += CTH) {
            int r = t / half, c = t - r * half;
            if (!((rv >> r) & 1ull))
                cp_async16(&tiles[r * NB + 2 * c], &g_mask[(size_t)r * NB + 2 * c]);
        }
        cp_async_commit();
    }
    cp_async_wait0();
    __syncthreads();

    int kept = 0;
    for (int ib = 0; ib < NB; ib++) {
        unsigned long long* tile = tiles + (size_t)(ib & 1) * TILE_WORDS;
        int ibe = ib & ~1;
        int off = ib - ibe;
        int wfull = NB - ibe;              // even
        // predicated prefetch of next tile (16B, even-column aligned)
        if (ib + 1 < NB) {
            int nb2 = ib + 1;
            int ibe2 = nb2 & ~1;
            int wfull2 = NB - ibe2;        // even
            int half2 = wfull2 >> 1;
            int rows2 = TOPN - nb2 * 64; if (rows2 > 64) rows2 = 64;
            unsigned long long rv = remv[nb2];
            unsigned long long* dst = tiles + (size_t)(nb2 & 1) * TILE_WORDS;
            for (int t = tid; t < rows2 * half2; t += CTH) {
                int r = t / half2, c = t - r * half2;
                if (!((rv >> r) & 1ull))
                    cp_async16(&dst[r * wfull2 + 2 * c],
                               &g_mask[(size_t)(nb2 * 64 + r) * NB + ibe2 + 2 * c]);
            }
        }
        cp_async_commit();

        int wcnt = NB - ib;
        unsigned long long rcur = remv[ib];
        unsigned long long acc = 0ull;
        int w = tid;                       // this thread owns word ib+w (w<wcnt)
        while (true) {
            unsigned long long avail = ~rcur;
            if (avail == 0ull) break;
            int bit = __ffsll((long long)avail) - 1;
            if (tid == 0) klist[kept] = ib * 64 + bit;
            kept++;
            rcur |= tile[bit * wfull + off] | (1ull << bit);   // self word + mark done
            if (w > 0 && w < wcnt) acc |= tile[bit * wfull + off + w];
            if (kept >= POSTN) break;
        }
        if (w > 0 && w < wcnt) remv[ib + w] |= acc;
        if (kept >= POSTN) break;
        cp_async_wait0();
        __syncthreads();
    }

    cp_async_wait0();
    __syncthreads();
    for (int t = tid; t < kept; t += CTH) {
        int idx = klist[t];
        float4 b = g_top_boxes[idx];
        float* row = out + t * 5;
        row[0] = 0.f; row[1] = b.x; row[2] = b.y; row[3] = b.z; row[4] = b.w;
    }
}

extern "C" void kernel_launch(void* const* d_in, const int* in_sizes, int n_in,
                              void* d_out, int out_size) {
    const float* scores  = (const float*)d_in[0];
    const float* deltas  = (const float*)d_in[1];
    const float* im_info = (const float*)d_in[2];
    float* out = (float*)d_out;

    void* p;
    cudaGetSymbolAddress(&p, g_z);
    cudaMemsetAsync(p, 0, sizeof(ZeroBlock));

    k_score_box<<<(NTOT + 255) / 256, 256>>>(scores, deltas, im_info);
    k_thresh<<<1, 256>>>();
    k_compact<<<(NTOT + 255) / 256, 256>>>();
    k_ranksc<<<CAND_MAX / 128, 128>>>();

    dim3 gm(NB, NB);
    k_mask<<<gm, 64>>>();

    size_t csh = (size_t)2 * TILE_WORDS * sizeof(unsigned long long);
    cudaFuncSetAttribute(k_collect, cudaFuncAttributeMaxDynamicSharedMemorySize, (int)csh);
    k_collect<<<1, CTH, csh>>>(out);
}

// round 12
// speedup vs baseline: 1.7889x; 1.3672x over previous
#include <cuda_runtime.h>
#include <cstdint>

#define HF 128
#define WF 192
#define NA 9
#define HW (HF*WF)               // 24576
#define NTOT (HW*NA)             // 221184
#define TOPN 6000
#define POSTN 300
#define NB 94                    // ceil(6000/64)
#define TILE_WORDS (64*NB)       // 6016
#define CAND_MAX 16384
#define CTH 512                  // collect threads
#define RTOP 1024                // early-NMS rank bound
#define RW 16                    // RTOP/64 words per row
#define RT 16                    // RTOP/64 tiles per side

__constant__ float c_anchors[NA][4] = {
    {-84.f,  -40.f,  99.f,  55.f},
    {-176.f, -88.f,  191.f, 103.f},
    {-360.f, -184.f, 375.f, 199.f},
    {-56.f,  -56.f,  71.f,  71.f},
    {-120.f, -120.f, 135.f, 135.f},
    {-248.f, -248.f, 263.f, 263.f},
    {-36.f,  -80.f,  51.f,  95.f},
    {-80.f,  -168.f, 95.f,  183.f},
    {-168.f, -344.f, 183.f, 359.f}
};

// single zeroed region (one memset node)
struct ZeroBlock {
    unsigned int hist[65536];
    unsigned long long sup[NB];
    unsigned int flag;           // 1 => early NMS insufficient, run fallback
};
__device__ __align__(16) ZeroBlock g_z;

__device__ unsigned int g_srt[NTOT];                 // 32-bit sortable score
__device__ float4 g_boxes[NTOT];                     // t = a*HW + k
__device__ __align__(16) unsigned int g_sfx[65536];  // sfx[b] = #keys in buckets > b
__device__ unsigned int g_thresh;
__device__ unsigned int g_cand_count;
__device__ __align__(16) unsigned long long g_cand[CAND_MAX];
__device__ float4 g_top_boxes[TOPN];
__device__ __align__(16) unsigned long long g_maskR[RTOP * RW];   // early mask
__device__ __align__(16) unsigned long long g_mask[6016 * NB];    // fallback mask

__device__ __forceinline__ void cp_async16(void* smem_dst, const void* gmem_src) {
    unsigned int d = (unsigned int)__cvta_generic_to_shared(smem_dst);
    asm volatile("cp.async.cg.shared.global [%0], [%1], 16;" :: "r"(d), "l"(gmem_src) : "memory");
}
__device__ __forceinline__ void cp_async_commit() {
    asm volatile("cp.async.commit_group;" ::: "memory");
}
__device__ __forceinline__ void cp_async_wait0() {
    asm volatile("cp.async.wait_group 0;" ::: "memory");
}

// ---------------- K1: decode + boxes + sortable score + histogram ----------------
__global__ void k_score_box(const float* __restrict__ scores,
                            const float* __restrict__ deltas,
                            const float* __restrict__ im_info) {
    int t = blockIdx.x * blockDim.x + threadIdx.x;
    if (t >= NTOT) return;
    int a = t / HW;
    int k = t - a * HW;
    int xs = k >> 7;          // meshgrid 'ij' quirk: shift row k -> (x=k/128, y=k%128)
    int ys = k & 127;

    float sc = scores[(NA + a) * HW + k];
    float dx = deltas[(4*a + 0) * HW + k];
    float dy = deltas[(4*a + 1) * HW + k];
    float dw = deltas[(4*a + 2) * HW + k];
    float dh = deltas[(4*a + 3) * HW + k];

    float sx = 16.f * (float)xs;
    float sy = 16.f * (float)ys;
    float ax1 = c_anchors[a][0] + sx;
    float ay1 = c_anchors[a][1] + sy;
    float ax2 = c_anchors[a][2] + sx;
    float ay2 = c_anchors[a][3] + sy;

    float w = ax2 - ax1 + 1.f;
    float h = ay2 - ay1 + 1.f;
    float cx = ax1 + 0.5f * w;
    float cy = ay1 + 0.5f * h;

    float pcx = dx * w + cx;
    float pcy = dy * h + cy;
    float pw = expf(dw) * w;
    float ph = expf(dh) * h;

    float x1 = pcx - 0.5f * pw;
    float y1 = pcy - 0.5f * ph;
    float x2 = pcx + 0.5f * pw;
    float y2 = pcy + 0.5f * ph;

    float im0 = im_info[0], im1 = im_info[1], im2 = im_info[2];
    x1 = fminf(fmaxf(x1, 0.f), im1 - 1.f);
    x2 = fminf(fmaxf(x2, 0.f), im1 - 1.f);
    y1 = fminf(fmaxf(y1, 0.f), im0 - 1.f);
    y2 = fminf(fmaxf(y2, 0.f), im0 - 1.f);

    float ms = 16.f * im2;
    bool valid = (x2 - x1 + 1.f >= ms) && (y2 - y1 + 1.f >= ms);

    unsigned int srt;
    if (valid) {
        unsigned int b = __float_as_uint(sc);
        srt = (b & 0x80000000u) ? ~b : (b | 0x80000000u);
    } else {
        srt = 0x007FFFFFu;   // flip(-inf)
    }
    g_srt[t] = srt;
    g_boxes[t] = make_float4(x1, y1, x2, y2);
    atomicAdd(&g_z.hist[srt >> 16], 1u);
}

// ---------------- K2: suffix table + threshold + candidate count ----------------
__global__ void k_thresh() {
    __shared__ unsigned int s[256];
    __shared__ unsigned int S2[256];
    __shared__ int gsel;
    __shared__ unsigned int above_s;
    int t = threadIdx.x;
    unsigned int sum = 0;
    const uint4* h4 = (const uint4*)g_z.hist;
#pragma unroll 8
    for (int b = 0; b < 64; b++) {
        uint4 v = h4[t * 64 + b];
        sum += v.x + v.y + v.z + v.w;
    }
    s[t] = sum;
    __syncthreads();
    for (int off = 1; off < 256; off <<= 1) {
        unsigned int v = (t + off < 256) ? s[t + off] : 0u;
        __syncthreads();
        s[t] += v;
        __syncthreads();
    }
    S2[t] = s[t];
    __syncthreads();

    {
        unsigned int run = (t == 255) ? 0u : S2[t + 1];
        uint4* s4 = (uint4*)g_sfx;
#pragma unroll 4
        for (int q = 63; q >= 0; q--) {
            int idx4 = t * 64 + q;
            uint4 h = h4[idx4];
            uint4 o;
            o.w = run; run += h.w;
            o.z = run; run += h.z;
            o.y = run; run += h.y;
            o.x = run; run += h.x;
            s4[idx4] = o;
        }
    }

    unsigned int nxt = (t == 255) ? 0u : S2[t + 1];
    if (S2[t] >= TOPN && nxt < TOPN) { gsel = t; above_s = nxt; }
    __syncthreads();
    int g = gsel;
    unsigned int above = above_s;
    unsigned int fv = g_z.hist[g * 256 + t];
    __syncthreads();
    s[t] = fv;
    __syncthreads();
    for (int off = 1; off < 256; off <<= 1) {
        unsigned int v = (t + off < 256) ? s[t + off] : 0u;
        __syncthreads();
        s[t] += v;
        __syncthreads();
    }
    unsigned int nxt2 = (t == 255) ? 0u : s[t + 1];
    if (above + s[t] >= TOPN && above + nxt2 < TOPN) {
        g_thresh = (unsigned int)(g * 256 + t);
        g_cand_count = above + s[t];
    }
}

// ---------------- K3: compact candidates into bucket-ordered slots ----------------
__global__ void k_compact() {
    int t = blockIdx.x * blockDim.x + threadIdx.x;
    if (t >= NTOT) return;
    unsigned int srt = g_srt[t];
    unsigned int b = srt >> 16;
    if (b >= g_thresh) {
        int a = t / HW;
        int k = t - a * HW;
        int i_ref = k * NA + a;   // reference flatten order (tiebreak)
        unsigned long long key =
            ((unsigned long long)srt << 32) | (0xFFFFFFFFu - (unsigned int)i_ref);
        unsigned int end = g_sfx[b - 1];                 // b >= thresh >= 1
        unsigned int old = atomicSub(&g_z.hist[b], 1u);  // counts down
        unsigned int slot = end - old;                   // bucket base .. end-1
        if (slot < CAND_MAX) g_cand[slot] = key;
    }
}

// ---------------- K4: in-bucket exact rank + gather + scatter ----------------
__global__ void k_ranksc() {
    unsigned int C = g_cand_count;
    if (C > CAND_MAX) C = CAND_MAX;
    int i = blockIdx.x * blockDim.x + threadIdx.x;
    if (i >= (int)C) return;
    unsigned long long mykey = g_cand[i];
    unsigned int b = (unsigned int)(mykey >> 48);

    unsigned int idx = 0xFFFFFFFFu - (unsigned int)(mykey & 0xFFFFFFFFull);
    int a = idx % NA;
    int k = idx / NA;
    float4 box = g_boxes[a * HW + k];
    unsigned int base = g_sfx[b];
    unsigned int end = g_sfx[b - 1];
    if (end > C) end = C;

    unsigned int rank = base;
    for (unsigned int j = base; j < end; j++)
        rank += (g_cand[j] > mykey) ? 1u : 0u;

    if (rank < TOPN) {
        g_top_boxes[rank] = box;
        bool vkey = ((unsigned int)(mykey >> 32)) > 0x007FFFFFu;
        if (!vkey) atomicOr(&g_z.sup[rank >> 6], 1ull << (rank & 63));
    }
}

// ---------------- K5a: early NMS bitmask, ranks < RTOP only ----------------
__global__ void k_maskR() {
    int bi = blockIdx.y, bj = blockIdx.x;
    if (bj < bi) return;
    int t = threadIdx.x;
    int i = bi * 64 + t;                 // < RTOP < TOPN
    __shared__ float4 bb[64];
    __shared__ float ar[64];
    int jg0 = bj * 64 + t;
    float4 b0 = g_top_boxes[jg0];
    bb[t] = b0;
    ar[t] = (b0.z - b0.x) * (b0.w - b0.y);
    __syncthreads();
    float4 bi_box = g_top_boxes[i];
    float area_i = (bi_box.z - bi_box.x) * (bi_box.w - bi_box.y);
    unsigned long long m = 0ull;
#pragma unroll 4
    for (int jj = 0; jj < 64; jj++) {
        int jg = bj * 64 + jj;
        float4 bj_box = bb[jj];
        float ix1 = fmaxf(bi_box.x, bj_box.x);
        float iy1 = fmaxf(bi_box.y, bj_box.y);
        float ix2 = fminf(bi_box.z, bj_box.z);
        float iy2 = fminf(bi_box.w, bj_box.w);
        float inter = fmaxf(ix2 - ix1, 0.f) * fmaxf(iy2 - iy1, 0.f);
        float denom = fmaxf(area_i + ar[jj] - inter, 1e-9f);
        float iou = inter / denom;
        if (iou > 0.7f && jg > i) m |= (1ull << jj);
    }
    g_maskR[i * RW + bj] = m;
}

// ---------------- K6a: early collect over ranks < RTOP (whole mask in smem) --
__global__ void __launch_bounds__(CTH) k_collectR(float* __restrict__ out) {
    __shared__ unsigned long long remv[RW];
    __shared__ int klist[POSTN];
    extern __shared__ unsigned long long tiles[];     // RTOP * RW = 16384 words
    int tid = threadIdx.x;

    for (int t = tid; t < POSTN * 5; t += CTH) out[t] = 0.f;   // d_out is poisoned
    if (tid < RW) remv[tid] = g_z.sup[tid];
    __syncthreads();

    // one-shot prefetch of the whole early-mask region (alive rows only)
    for (int t = tid; t < RTOP * (RW / 2); t += CTH) {
        int r = t >> 3;                   // row (rank)
        int c = t & 7;                    // 16B chunk
        if (!((remv[r >> 6] >> (r & 63)) & 1ull))
            cp_async16(&tiles[r * RW + 2 * c], &g_maskR[r * RW + 2 * c]);
    }
    cp_async_commit();
    cp_async_wait0();
    __syncthreads();

    int kept = 0;
    for (int ib = 0; ib < RT; ib++) {
        unsigned long long rcur = remv[ib];
        unsigned long long acc = 0ull;
        int w = tid;                      // owns word ib+w, 0 < w < RW-ib
        while (true) {
            unsigned long long avail = ~rcur;
            if (avail == 0ull) break;
            int bit = __ffsll((long long)avail) - 1;
            int i = ib * 64 + bit;
            if (tid == 0) klist[kept] = i;
            kept++;
            rcur |= tiles[i * RW + ib] | (1ull << bit);
            if (w > 0 && w < RW - ib) acc |= tiles[i * RW + ib + w];
            if (kept >= POSTN) break;
        }
        if (w > 0 && w < RW - ib) remv[ib + w] |= acc;
        if (kept >= POSTN) break;
        __syncthreads();
    }
    __syncthreads();

    if (kept >= POSTN) {
        for (int t = tid; t < POSTN; t += CTH) {
            int idx = klist[t];
            float4 b = g_top_boxes[idx];
            float* row = out + t * 5;
            row[0] = 0.f; row[1] = b.x; row[2] = b.y; row[3] = b.z; row[4] = b.w;
        }
    } else if (tid == 0) {
        g_z.flag = 1;                     // fallback needed
    }
}

// ---------------- K5b: fallback full mask (gated on flag) ----------------
__global__ void k_mask() {
    if (g_z.flag == 0) return;
    int bi = blockIdx.y, bj = blockIdx.x;
    if (bj < bi) return;
    int t = threadIdx.x;
    int i = bi * 64 + t;
    __shared__ float4 bb[64];
    __shared__ float ar[64];
    int jg0 = bj * 64 + t;
    if (jg0 < TOPN) {
        float4 b = g_top_boxes[jg0];
        bb[t] = b;
        ar[t] = (b.z - b.x) * (b.w - b.y);
    } else {
        bb[t] = make_float4(0.f, 0.f, 0.f, 0.f);
        ar[t] = 0.f;
    }
    __syncthreads();
    if (i >= TOPN) return;
    float4 bi_box = g_top_boxes[i];
    float area_i = (bi_box.z - bi_box.x) * (bi_box.w - bi_box.y);
    unsigned long long m = 0ull;
#pragma unroll 4
    for (int jj = 0; jj < 64; jj++) {
        int jg = bj * 64 + jj;
        float4 bj_box = bb[jj];
        float ix1 = fmaxf(bi_box.x, bj_box.x);
        float iy1 = fmaxf(bi_box.y, bj_box.y);
        float ix2 = fminf(bi_box.z, bj_box.z);
        float iy2 = fminf(bi_box.w, bj_box.w);
        float inter = fmaxf(ix2 - ix1, 0.f) * fmaxf(iy2 - iy1, 0.f);
        float denom = fmaxf(area_i + ar[jj] - inter, 1e-9f);
        float iou = inter / denom;
        if (iou > 0.7f && jg > i && jg < TOPN) m |= (1ull << jj);
    }
    g_mask[(size_t)i * NB + bj] = m;
}

// ---------------- K6b: fallback full collect (gated on flag) ----------------
__global__ void __launch_bounds__(CTH) k_collect(float* __restrict__ out) {
    if (g_z.flag == 0) return;
    __shared__ unsigned long long remv[NB];
    __shared__ int klist[POSTN];
    extern __shared__ unsigned long long tiles[];  // 2 * TILE_WORDS
    int tid = threadIdx.x;

    for (int t = tid; t < NB; t += CTH) {
        unsigned long long m = g_z.sup[t];
        if (t == NB - 1) m |= 0xFFFF000000000000ull;   // bits >= 6000
        remv[t] = m;
    }
    __syncthreads();

    {
        unsigned long long rv = remv[0];
        const int half = NB / 2;
        for (int t = tid; t < 64 * half; t += CTH) {
            int r = t / half, c = t - r * half;
            if (!((rv >> r) & 1ull))
                cp_async16(&tiles[r * NB + 2 * c], &g_mask[(size_t)r * NB + 2 * c]);
        }
        cp_async_commit();
    }
    cp_async_wait0();
    __syncthreads();

    int kept = 0;
    for (int ib = 0; ib < NB; ib++) {
        unsigned long long* tile = tiles + (size_t)(ib & 1) * TILE_WORDS;
        int ibe = ib & ~1;
        int off = ib - ibe;
        int wfull = NB - ibe;
        if (ib + 1 < NB) {
            int nb2 = ib + 1;
            int ibe2 = nb2 & ~1;
            int wfull2 = NB - ibe2;
            int half2 = wfull2 >> 1;
            int rows2 = TOPN - nb2 * 64; if (rows2 > 64) rows2 = 64;
            unsigned long long rv = remv[nb2];
            unsigned long long* dst = tiles + (size_t)(nb2 & 1) * TILE_WORDS;
            for (int t = tid; t < rows2 * half2; t += CTH) {
                int r = t / half2, c = t - r * half2;
                if (!((rv >> r) & 1ull))
                    cp_async16(&dst[r * wfull2 + 2 * c],
                               &g_mask[(size_t)(nb2 * 64 + r) * NB + ibe2 + 2 * c]);
            }
        }
        cp_async_commit();

        int wcnt = NB - ib;
        unsigned long long rcur = remv[ib];
        unsigned long long acc = 0ull;
        int w = tid;
        while (true) {
            unsigned long long avail = ~rcur;
            if (avail == 0ull) break;
            int bit = __ffsll((long long)avail) - 1;
            if (tid == 0) klist[kept] = ib * 64 + bit;
            kept++;
            rcur |= tile[bit * wfull + off] | (1ull << bit);
            if (w > 0 && w < wcnt) acc |= tile[bit * wfull + off + w];
            if (kept >= POSTN) break;
        }
        if (w > 0 && w < wcnt) remv[ib + w] |= acc;
        if (kept >= POSTN) break;
        cp_async_wait0();
        __syncthreads();
    }

    cp_async_wait0();
    __syncthreads();
    for (int t = tid; t < kept; t += CTH) {
        int idx = klist[t];
        float4 b = g_top_boxes[idx];
        float* row = out + t * 5;
        row[0] = 0.f; row[1] = b.x; row[2] = b.y; row[3] = b.z; row[4] = b.w;
    }
}

extern "C" void kernel_launch(void* const* d_in, const int* in_sizes, int n_in,
                              void* d_out, int out_size) {
    const float* scores  = (const float*)d_in[0];
    const float* deltas  = (const float*)d_in[1];
    const float* im_info = (const float*)d_in[2];
    float* out = (float*)d_out;

    void* p;
    cudaGetSymbolAddress(&p, g_z);
    cudaMemsetAsync(p, 0, sizeof(ZeroBlock));

    k_score_box<<<(NTOT + 255) / 256, 256>>>(scores, deltas, im_info);
    k_thresh<<<1, 256>>>();
    k_compact<<<(NTOT + 255) / 256, 256>>>();
    k_ranksc<<<CAND_MAX / 128, 128>>>();

    dim3 gmr(RT, RT);
    k_maskR<<<gmr, 64>>>();

    size_t rsh = (size_t)RTOP * RW * sizeof(unsigned long long);   // 128 KB
    cudaFuncSetAttribute(k_collectR, cudaFuncAttributeMaxDynamicSharedMemorySize, (int)rsh);
    k_collectR<<<1, CTH, rsh>>>(out);

    dim3 gm(NB, NB);
    k_mask<<<gm, 64>>>();

    size_t csh = (size_t)2 * TILE_WORDS * sizeof(unsigned long long);
    cudaFuncSetAttribute(k_collect, cudaFuncAttributeMaxDynamicSharedMemorySize, (int)csh);
    k_collect<<<1, CTH, csh>>>(out);
}

// round 13
// speedup vs baseline: 1.8191x; 1.0169x over previous
#include <cuda_runtime.h>
#include <cstdint>

#define HF 128
#define WF 192
#define NA 9
#define HW (HF*WF)               // 24576
#define NTOT (HW*NA)             // 221184
#define TOPN 6000
#define POSTN 300
#define NB 94                    // ceil(6000/64)
#define TILE_WORDS (64*NB)       // 6016
#define CAND_MAX 16384
#define CTH 512                  // collect threads
#define RTOP 1024                // early-NMS rank bound
#define RW 16                    // RTOP/64 words per row
#define RT 16                    // RTOP/64 tiles per side

__constant__ float c_anchors[NA][4] = {
    {-84.f,  -40.f,  99.f,  55.f},
    {-176.f, -88.f,  191.f, 103.f},
    {-360.f, -184.f, 375.f, 199.f},
    {-56.f,  -56.f,  71.f,  71.f},
    {-120.f, -120.f, 135.f, 135.f},
    {-248.f, -248.f, 263.f, 263.f},
    {-36.f,  -80.f,  51.f,  95.f},
    {-80.f,  -168.f, 95.f,  183.f},
    {-168.f, -344.f, 183.f, 359.f}
};

// single zeroed region (one memset node)
struct ZeroBlock {
    unsigned int hist[65536];
    unsigned long long sup[NB];
    unsigned int flag;           // 1 => early NMS insufficient, run fallback
};
__device__ __align__(16) ZeroBlock g_z;

__device__ unsigned int g_srt[NTOT];                 // 32-bit sortable score
__device__ float4 g_boxes[NTOT];                     // t = a*HW + k
__device__ __align__(16) unsigned int g_sfx[65536];  // sfx[b] = #keys in buckets > b
__device__ unsigned int g_thresh;
__device__ unsigned int g_cand_count;
__device__ __align__(16) unsigned long long g_cand[CAND_MAX];
__device__ float4 g_top_boxes[TOPN];
__device__ __align__(16) unsigned long long g_maskR[RTOP * RW];   // early mask
__device__ __align__(16) unsigned long long g_mask[6016 * NB];    // fallback mask

__device__ __forceinline__ void cp_async16(void* smem_dst, const void* gmem_src) {
    unsigned int d = (unsigned int)__cvta_generic_to_shared(smem_dst);
    asm volatile("cp.async.cg.shared.global [%0], [%1], 16;" :: "r"(d), "l"(gmem_src) : "memory");
}
__device__ __forceinline__ void cp_async_commit() {
    asm volatile("cp.async.commit_group;" ::: "memory");
}
__device__ __forceinline__ void cp_async_wait0() {
    asm volatile("cp.async.wait_group 0;" ::: "memory");
}

// ---------------- K1: decode + boxes + sortable score + histogram ----------------
__global__ void k_score_box(const float* __restrict__ scores,
                            const float* __restrict__ deltas,
                            const float* __restrict__ im_info) {
    int t = blockIdx.x * blockDim.x + threadIdx.x;
    if (t >= NTOT) return;
    int a = t / HW;
    int k = t - a * HW;
    int xs = k >> 7;          // meshgrid 'ij' quirk: shift row k -> (x=k/128, y=k%128)
    int ys = k & 127;

    float sc = scores[(NA + a) * HW + k];
    float dx = deltas[(4*a + 0) * HW + k];
    float dy = deltas[(4*a + 1) * HW + k];
    float dw = deltas[(4*a + 2) * HW + k];
    float dh = deltas[(4*a + 3) * HW + k];

    float sx = 16.f * (float)xs;
    float sy = 16.f * (float)ys;
    float ax1 = c_anchors[a][0] + sx;
    float ay1 = c_anchors[a][1] + sy;
    float ax2 = c_anchors[a][2] + sx;
    float ay2 = c_anchors[a][3] + sy;

    float w = ax2 - ax1 + 1.f;
    float h = ay2 - ay1 + 1.f;
    float cx = ax1 + 0.5f * w;
    float cy = ay1 + 0.5f * h;

    float pcx = dx * w + cx;
    float pcy = dy * h + cy;
    float pw = expf(dw) * w;
    float ph = expf(dh) * h;

    float x1 = pcx - 0.5f * pw;
    float y1 = pcy - 0.5f * ph;
    float x2 = pcx + 0.5f * pw;
    float y2 = pcy + 0.5f * ph;

    float im0 = im_info[0], im1 = im_info[1], im2 = im_info[2];
    x1 = fminf(fmaxf(x1, 0.f), im1 - 1.f);
    x2 = fminf(fmaxf(x2, 0.f), im1 - 1.f);
    y1 = fminf(fmaxf(y1, 0.f), im0 - 1.f);
    y2 = fminf(fmaxf(y2, 0.f), im0 - 1.f);

    float ms = 16.f * im2;
    bool valid = (x2 - x1 + 1.f >= ms) && (y2 - y1 + 1.f >= ms);

    unsigned int srt;
    if (valid) {
        unsigned int b = __float_as_uint(sc);
        srt = (b & 0x80000000u) ? ~b : (b | 0x80000000u);
    } else {
        srt = 0x007FFFFFu;   // flip(-inf)
    }
    g_srt[t] = srt;
    g_boxes[t] = make_float4(x1, y1, x2, y2);
    atomicAdd(&g_z.hist[srt >> 16], 1u);
}

// ---------------- K2: suffix table + threshold (1024 threads) ----------------
__global__ void __launch_bounds__(1024) k_thresh() {
    __shared__ unsigned int part[256][4];
    __shared__ unsigned int s[256];
    __shared__ unsigned int S2[256];
    __shared__ int gsel;
    __shared__ unsigned int above_s;
    int t = threadIdx.x;
    int g = t >> 2, q = t & 3;
    const uint4* h4 = (const uint4*)g_z.hist;

    // quarter partial sums: each thread reads 16 uint4
    {
        unsigned int sum = 0;
#pragma unroll
        for (int b = 0; b < 16; b++) {
            uint4 v = h4[g * 64 + q * 16 + b];
            sum += v.x + v.y + v.z + v.w;
        }
        part[g][q] = sum;
    }
    __syncthreads();
    if (t < 256) s[t] = part[t][0] + part[t][1] + part[t][2] + part[t][3];
    __syncthreads();
    for (int off = 1; off < 256; off <<= 1) {
        unsigned int v = 0;
        if (t < 256) v = (t + off < 256) ? s[t + off] : 0u;
        __syncthreads();
        if (t < 256) s[t] += v;
        __syncthreads();
    }
    if (t < 256) S2[t] = s[t];
    __syncthreads();

    // suffix-table fill: each thread fills its 16 uint4 quarter
    {
        unsigned int run = (g == 255) ? 0u : S2[g + 1];
#pragma unroll
        for (int qq = 3; qq > 0; qq--) if (qq > q) run += part[g][qq];
        uint4* s4 = (uint4*)g_sfx;
#pragma unroll
        for (int b = 15; b >= 0; b--) {
            int idx4 = g * 64 + q * 16 + b;
            uint4 h = h4[idx4];
            uint4 o;
            o.w = run; run += h.w;
            o.z = run; run += h.z;
            o.y = run; run += h.y;
            o.x = run; run += h.x;
            s4[idx4] = o;
        }
    }

    // threshold search (256-thread path, block-wide barriers)
    if (t < 256) {
        unsigned int nxt = (t == 255) ? 0u : S2[t + 1];
        if (S2[t] >= TOPN && nxt < TOPN) { gsel = t; above_s = nxt; }
    }
    __syncthreads();
    int gg = gsel;
    unsigned int above = above_s;
    unsigned int fv = 0;
    if (t < 256) fv = g_z.hist[gg * 256 + t];
    __syncthreads();
    if (t < 256) s[t] = fv;
    __syncthreads();
    for (int off = 1; off < 256; off <<= 1) {
        unsigned int v = 0;
        if (t < 256) v = (t + off < 256) ? s[t + off] : 0u;
        __syncthreads();
        if (t < 256) s[t] += v;
        __syncthreads();
    }
    if (t < 256) {
        unsigned int nxt2 = (t == 255) ? 0u : s[t + 1];
        if (above + s[t] >= TOPN && above + nxt2 < TOPN) {
            g_thresh = (unsigned int)(gg * 256 + t);
            g_cand_count = above + s[t];
        }
    }
}

// ---------------- K3: compact candidates into bucket-ordered slots ----------------
__global__ void k_compact() {
    int t = blockIdx.x * blockDim.x + threadIdx.x;
    if (t >= NTOT) return;
    unsigned int srt = g_srt[t];
    unsigned int b = srt >> 16;
    if (b >= g_thresh) {
        int a = t / HW;
        int k = t - a * HW;
        int i_ref = k * NA + a;   // reference flatten order (tiebreak)
        unsigned long long key =
            ((unsigned long long)srt << 32) | (0xFFFFFFFFu - (unsigned int)i_ref);
        unsigned int end = g_sfx[b - 1];                 // b >= thresh >= 1
        unsigned int old = atomicSub(&g_z.hist[b], 1u);  // counts down
        unsigned int slot = end - old;                   // bucket base .. end-1
        if (slot < CAND_MAX) g_cand[slot] = key;
    }
}

// ---------------- K4: in-bucket exact rank + gather + scatter ----------------
__global__ void k_ranksc() {
    unsigned int C = g_cand_count;
    if (C > CAND_MAX) C = CAND_MAX;
    int i = blockIdx.x * blockDim.x + threadIdx.x;
    if (i >= (int)C) return;
    unsigned long long mykey = g_cand[i];
    unsigned int b = (unsigned int)(mykey >> 48);

    unsigned int idx = 0xFFFFFFFFu - (unsigned int)(mykey & 0xFFFFFFFFull);
    int a = idx % NA;
    int k = idx / NA;
    float4 box = g_boxes[a * HW + k];
    unsigned int base = g_sfx[b];
    unsigned int end = g_sfx[b - 1];
    if (end > C) end = C;

    unsigned int rank = base;
    for (unsigned int j = base; j < end; j++)
        rank += (g_cand[j] > mykey) ? 1u : 0u;

    if (rank < TOPN) {
        g_top_boxes[rank] = box;
        bool vkey = ((unsigned int)(mykey >> 32)) > 0x007FFFFFu;
        if (!vkey) atomicOr(&g_z.sup[rank >> 6], 1ull << (rank & 63));
    }
}

// ---------------- K5a: early NMS bitmask, ranks < RTOP only ----------------
__global__ void k_maskR() {
    int bi = blockIdx.y, bj = blockIdx.x;
    if (bj < bi) return;
    int t = threadIdx.x;
    int i = bi * 64 + t;                 // < RTOP < TOPN
    __shared__ float4 bb[64];
    __shared__ float ar[64];
    int jg0 = bj * 64 + t;
    float4 b0 = g_top_boxes[jg0];
    bb[t] = b0;
    ar[t] = (b0.z - b0.x) * (b0.w - b0.y);
    __syncthreads();
    float4 bi_box = g_top_boxes[i];
    float area_i = (bi_box.z - bi_box.x) * (bi_box.w - bi_box.y);
    unsigned long long m = 0ull;
#pragma unroll 4
    for (int jj = 0; jj < 64; jj++) {
        int jg = bj * 64 + jj;
        float4 bj_box = bb[jj];
        float ix1 = fmaxf(bi_box.x, bj_box.x);
        float iy1 = fmaxf(bi_box.y, bj_box.y);
        float ix2 = fminf(bi_box.z, bj_box.z);
        float iy2 = fminf(bi_box.w, bj_box.w);
        float inter = fmaxf(ix2 - ix1, 0.f) * fmaxf(iy2 - iy1, 0.f);
        float denom = fmaxf(area_i + ar[jj] - inter, 1e-9f);
        float iou = inter / denom;
        if (iou > 0.7f && jg > i) m |= (1ull << jj);
    }
    g_maskR[i * RW + bj] = m;
}

// ---------------- K6a: early collect, per-tile sparse double-buffered staging --
__global__ void __launch_bounds__(CTH) k_collectR(float* __restrict__ out) {
    __shared__ unsigned long long remv[RW];
    __shared__ int klist[POSTN];
    __shared__ unsigned long long tiles[2][64 * RW];   // 16 KB
    int tid = threadIdx.x;

    for (int t = tid; t < POSTN * 5; t += CTH) out[t] = 0.f;   // d_out is poisoned
    if (tid < RW) remv[tid] = g_z.sup[tid];
    __syncthreads();

    // prefetch tile 0 (ibe=0, wfull=RW): alive rows only
    {
        unsigned long long rv = remv[0];
        for (int t = tid; t < 64 * (RW / 2); t += CTH) {
            int r = t >> 3, c = t & 7;
            if (!((rv >> r) & 1ull))
                cp_async16(&tiles[0][r * RW + 2 * c], &g_maskR[r * RW + 2 * c]);
        }
        cp_async_commit();
    }
    cp_async_wait0();
    __syncthreads();

    int kept = 0;
    for (int ib = 0; ib < RT; ib++) {
        unsigned long long* tile = tiles[ib & 1];
        int ibe = ib & ~1;
        int off = ib - ibe;
        int wfull = RW - ibe;              // even
        // predicated prefetch of next tile (suppression only grows -> safe)
        if (ib + 1 < RT) {
            int nb2 = ib + 1;
            int ibe2 = nb2 & ~1;
            int wfull2 = RW - ibe2;        // even
            int half2 = wfull2 >> 1;
            unsigned long long rv = remv[nb2];
            unsigned long long* dst = tiles[nb2 & 1];
            for (int t = tid; t < 64 * half2; t += CTH) {
                int r = t / half2, c = t - r * half2;
                if (!((rv >> r) & 1ull))
                    cp_async16(&dst[r * wfull2 + 2 * c],
                               &g_maskR[(nb2 * 64 + r) * RW + ibe2 + 2 * c]);
            }
        }
        cp_async_commit();

        int wcnt = RW - ib;
        unsigned long long rcur = remv[ib];
        unsigned long long acc = 0ull;
        int w = tid;                       // owns word ib+w (0 < w < wcnt)
        while (true) {
            unsigned long long avail = ~rcur;
            if (avail == 0ull) break;
            int bit = __ffsll((long long)avail) - 1;
            if (tid == 0) klist[kept] = ib * 64 + bit;
            kept++;
            rcur |= tile[bit * wfull + off] | (1ull << bit);
            if (w > 0 && w < wcnt) acc |= tile[bit * wfull + off + w];
            if (kept >= POSTN) break;
        }
        if (w > 0 && w < wcnt) remv[ib + w] |= acc;
        if (kept >= POSTN) break;
        cp_async_wait0();
        __syncthreads();
    }
    cp_async_wait0();
    __syncthreads();

    if (kept >= POSTN) {
        for (int t = tid; t < POSTN; t += CTH) {
            int idx = klist[t];
            float4 b = g_top_boxes[idx];
            float* row = out + t * 5;
            row[0] = 0.f; row[1] = b.x; row[2] = b.y; row[3] = b.z; row[4] = b.w;
        }
    } else if (tid == 0) {
        g_z.flag = 1;                     // fallback needed
    }
}

// ---------------- K5b: fallback full mask (gated on flag) ----------------
__global__ void k_mask() {
    if (g_z.flag == 0) return;
    int bi = blockIdx.y, bj = blockIdx.x;
    if (bj < bi) return;
    int t = threadIdx.x;
    int i = bi * 64 + t;
    __shared__ float4 bb[64];
    __shared__ float ar[64];
    int jg0 = bj * 64 + t;
    if (jg0 < TOPN) {
        float4 b = g_top_boxes[jg0];
        bb[t] = b;
        ar[t] = (b.z - b.x) * (b.w - b.y);
    } else {
        bb[t] = make_float4(0.f, 0.f, 0.f, 0.f);
        ar[t] = 0.f;
    }
    __syncthreads();
    if (i >= TOPN) return;
    float4 bi_box = g_top_boxes[i];
    float area_i = (bi_box.z - bi_box.x) * (bi_box.w - bi_box.y);
    unsigned long long m = 0ull;
#pragma unroll 4
    for (int jj = 0; jj < 64; jj++) {
        int jg = bj * 64 + jj;
        float4 bj_box = bb[jj];
        float ix1 = fmaxf(bi_box.x, bj_box.x);
        float iy1 = fmaxf(bi_box.y, bj_box.y);
        float ix2 = fminf(bi_box.z, bj_box.z);
        float iy2 = fminf(bi_box.w, bj_box.w);
        float inter = fmaxf(ix2 - ix1, 0.f) * fmaxf(iy2 - iy1, 0.f);
        float denom = fmaxf(area_i + ar[jj] - inter, 1e-9f);
        float iou = inter / denom;
        if (iou > 0.7f && jg > i && jg < TOPN) m |= (1ull << jj);
    }
    g_mask[(size_t)i * NB + bj] = m;
}

// ---------------- K6b: fallback full collect (gated on flag) ----------------
__global__ void __launch_bounds__(CTH) k_collect(float* __restrict__ out) {
    if (g_z.flag == 0) return;
    __shared__ unsigned long long remv[NB];
    __shared__ int klist[POSTN];
    extern __shared__ unsigned long long tiles[];  // 2 * TILE_WORDS
    int tid = threadIdx.x;

    for (int t = tid; t < NB; t += CTH) {
        unsigned long long m = g_z.sup[t];
        if (t == NB - 1) m |= 0xFFFF000000000000ull;   // bits >= 6000
        remv[t] = m;
    }
    __syncthreads();

    {
        unsigned long long rv = remv[0];
        const int half = NB / 2;
        for (int t = tid; t < 64 * half; t += CTH) {
            int r = t / half, c = t - r * half;
            if (!((rv >> r) & 1ull))
                cp_async16(&tiles[r * NB + 2 * c], &g_mask[(size_t)r * NB + 2 * c]);
        }
        cp_async_commit();
    }
    cp_async_wait0();
    __syncthreads();

    int kept = 0;
    for (int ib = 0; ib < NB; ib++) {
        unsigned long long* tile = tiles + (size_t)(ib & 1) * TILE_WORDS;
        int ibe = ib & ~1;
        int off = ib - ibe;
        int wfull = NB - ibe;
        if (ib + 1 < NB) {
            int nb2 = ib + 1;
            int ibe2 = nb2 & ~1;
            int wfull2 = NB - ibe2;
            int half2 = wfull2 >> 1;
            int rows2 = TOPN - nb2 * 64; if (rows2 > 64) rows2 = 64;
            unsigned long long rv = remv[nb2];
            unsigned long long* dst = tiles + (size_t)(nb2 & 1) * TILE_WORDS;
            for (int t = tid; t < rows2 * half2; t += CTH) {
                int r = t / half2, c = t - r * half2;
                if (!((rv >> r) & 1ull))
                    cp_async16(&dst[r * wfull2 + 2 * c],
                               &g_mask[(size_t)(nb2 * 64 + r) * NB + ibe2 + 2 * c]);
            }
        }
        cp_async_commit();

        int wcnt = NB - ib;
        unsigned long long rcur = remv[ib];
        unsigned long long acc = 0ull;
        int w = tid;
        while (true) {
            unsigned long long avail = ~rcur;
            if (avail == 0ull) break;
            int bit = __ffsll((long long)avail) - 1;
            if (tid == 0) klist[kept] = ib * 64 + bit;
            kept++;
            rcur |= tile[bit * wfull + off] | (1ull << bit);
            if (w > 0 && w < wcnt) acc |= tile[bit * wfull + off + w];
            if (kept >= POSTN) break;
        }
        if (w > 0 && w < wcnt) remv[ib + w] |= acc;
        if (kept >= POSTN) break;
        cp_async_wait0();
        __syncthreads();
    }

    cp_async_wait0();
    __syncthreads();
    for (int t = tid; t < kept; t += CTH) {
        int idx = klist[t];
        float4 b = g_top_boxes[idx];
        float* row = out + t * 5;
        row[0] = 0.f; row[1] = b.x; row[2] = b.y; row[3] = b.z; row[4] = b.w;
    }
}

extern "C" void kernel_launch(void* const* d_in, const int* in_sizes, int n_in,
                              void* d_out, int out_size) {
    const float* scores  = (const float*)d_in[0];
    const float* deltas  = (const float*)d_in[1];
    const float* im_info = (const float*)d_in[2];
    float* out = (float*)d_out;

    void* p;
    cudaGetSymbolAddress(&p, g_z);
    cudaMemsetAsync(p, 0, sizeof(ZeroBlock));

    k_score_box<<<(NTOT + 255) / 256, 256>>>(scores, deltas, im_info);
    k_thresh<<<1, 1024>>>();
    k_compact<<<(NTOT + 255) / 256, 256>>>();
    k_ranksc<<<CAND_MAX / 128, 128>>>();

    dim3 gmr(RT, RT);
    k_maskR<<<gmr, 64>>>();
    k_collectR<<<1, CTH>>>(out);

    dim3 gm(NB, NB);
    k_mask<<<gm, 64>>>();

    size_t csh = (size_t)2 * TILE_WORDS * sizeof(unsigned long long);
    cudaFuncSetAttribute(k_collect, cudaFuncAttributeMaxDynamicSharedMemorySize, (int)csh);
    k_collect<<<1, CTH, csh>>>(out);
}

// round 14
// speedup vs baseline: 1.8868x; 1.0372x over previous
#include <cuda_runtime.h>
#include <cstdint>

#define HF 128
#define WF 192
#define NA 9
#define HW (HF*WF)               // 24576
#define NTOT (HW*NA)             // 221184
#define TOPN 6000
#define POSTN 300
#define NB 94                    // ceil(6000/64) (sup words)
#define CAND_MAX 16384
#define CTH 512                  // collect threads
#define RTOP 1024                // early-NMS rank bound
#define RW 16                    // RTOP/64 words per row
#define RT 16                    // RTOP/64 tiles per side

__constant__ float c_anchors[NA][4] = {
    {-84.f,  -40.f,  99.f,  55.f},
    {-176.f, -88.f,  191.f, 103.f},
    {-360.f, -184.f, 375.f, 199.f},
    {-56.f,  -56.f,  71.f,  71.f},
    {-120.f, -120.f, 135.f, 135.f},
    {-248.f, -248.f, 263.f, 263.f},
    {-36.f,  -80.f,  51.f,  95.f},
    {-80.f,  -168.f, 95.f,  183.f},
    {-168.f, -344.f, 183.f, 359.f}
};

// single zeroed region (one memset node)
struct ZeroBlock {
    unsigned int hist[65536];
    unsigned long long sup[NB];
};
__device__ __align__(16) ZeroBlock g_z;

__device__ unsigned int g_srt[NTOT];                 // 32-bit sortable score
__device__ float4 g_boxes[NTOT];                     // t = a*HW + k
__device__ __align__(16) unsigned int g_sfx[65536];  // sfx[b] = #keys in buckets > b
__device__ unsigned int g_thresh;
__device__ unsigned int g_cand_count;
__device__ __align__(16) unsigned long long g_cand[CAND_MAX];
__device__ float4 g_top_boxes[TOPN];
__device__ __align__(16) unsigned long long g_maskR[RTOP * RW];   // early mask

__device__ __forceinline__ void cp_async16(void* smem_dst, const void* gmem_src) {
    unsigned int d = (unsigned int)__cvta_generic_to_shared(smem_dst);
    asm volatile("cp.async.cg.shared.global [%0], [%1], 16;" :: "r"(d), "l"(gmem_src) : "memory");
}
__device__ __forceinline__ void cp_async_commit() {
    asm volatile("cp.async.commit_group;" ::: "memory");
}
__device__ __forceinline__ void cp_async_wait0() {
    asm volatile("cp.async.wait_group 0;" ::: "memory");
}

// ---------------- K1: decode + boxes + sortable score + histogram ----------------
__global__ void k_score_box(const float* __restrict__ scores,
                            const float* __restrict__ deltas,
                            const float* __restrict__ im_info) {
    int t = blockIdx.x * blockDim.x + threadIdx.x;
    if (t >= NTOT) return;
    int a = t / HW;
    int k = t - a * HW;
    int xs = k >> 7;          // meshgrid 'ij' quirk: shift row k -> (x=k/128, y=k%128)
    int ys = k & 127;

    float sc = scores[(NA + a) * HW + k];
    float dx = deltas[(4*a + 0) * HW + k];
    float dy = deltas[(4*a + 1) * HW + k];
    float dw = deltas[(4*a + 2) * HW + k];
    float dh = deltas[(4*a + 3) * HW + k];

    float sx = 16.f * (float)xs;
    float sy = 16.f * (float)ys;
    float ax1 = c_anchors[a][0] + sx;
    float ay1 = c_anchors[a][1] + sy;
    float ax2 = c_anchors[a][2] + sx;
    float ay2 = c_anchors[a][3] + sy;

    float w = ax2 - ax1 + 1.f;
    float h = ay2 - ay1 + 1.f;
    float cx = ax1 + 0.5f * w;
    float cy = ay1 + 0.5f * h;

    float pcx = dx * w + cx;
    float pcy = dy * h + cy;
    float pw = expf(dw) * w;
    float ph = expf(dh) * h;

    float x1 = pcx - 0.5f * pw;
    float y1 = pcy - 0.5f * ph;
    float x2 = pcx + 0.5f * pw;
    float y2 = pcy + 0.5f * ph;

    float im0 = im_info[0], im1 = im_info[1], im2 = im_info[2];
    x1 = fminf(fmaxf(x1, 0.f), im1 - 1.f);
    x2 = fminf(fmaxf(x2, 0.f), im1 - 1.f);
    y1 = fminf(fmaxf(y1, 0.f), im0 - 1.f);
    y2 = fminf(fmaxf(y2, 0.f), im0 - 1.f);

    float ms = 16.f * im2;
    bool valid = (x2 - x1 + 1.f >= ms) && (y2 - y1 + 1.f >= ms);

    unsigned int srt;
    if (valid) {
        unsigned int b = __float_as_uint(sc);
        srt = (b & 0x80000000u) ? ~b : (b | 0x80000000u);
    } else {
        srt = 0x007FFFFFu;   // flip(-inf)
    }
    g_srt[t] = srt;
    g_boxes[t] = make_float4(x1, y1, x2, y2);
    atomicAdd(&g_z.hist[srt >> 16], 1u);
}

// ---------------- K2: suffix table + threshold (1024 threads) ----------------
__global__ void __launch_bounds__(1024) k_thresh() {
    __shared__ unsigned int part[256][4];
    __shared__ unsigned int s[256];
    __shared__ unsigned int S2[256];
    __shared__ int gsel;
    __shared__ unsigned int above_s;
    int t = threadIdx.x;
    int g = t >> 2, q = t & 3;
    const uint4* h4 = (const uint4*)g_z.hist;

    {
        unsigned int sum = 0;
#pragma unroll
        for (int b = 0; b < 16; b++) {
            uint4 v = h4[g * 64 + q * 16 + b];
            sum += v.x + v.y + v.z + v.w;
        }
        part[g][q] = sum;
    }
    __syncthreads();
    if (t < 256) s[t] = part[t][0] + part[t][1] + part[t][2] + part[t][3];
    __syncthreads();
    for (int off = 1; off < 256; off <<= 1) {
        unsigned int v = 0;
        if (t < 256) v = (t + off < 256) ? s[t + off] : 0u;
        __syncthreads();
        if (t < 256) s[t] += v;
        __syncthreads();
    }
    if (t < 256) S2[t] = s[t];
    __syncthreads();

    {
        unsigned int run = (g == 255) ? 0u : S2[g + 1];
#pragma unroll
        for (int qq = 3; qq > 0; qq--) if (qq > q) run += part[g][qq];
        uint4* s4 = (uint4*)g_sfx;
#pragma unroll
        for (int b = 15; b >= 0; b--) {
            int idx4 = g * 64 + q * 16 + b;
            uint4 h = h4[idx4];
            uint4 o;
            o.w = run; run += h.w;
            o.z = run; run += h.z;
            o.y = run; run += h.y;
            o.x = run; run += h.x;
            s4[idx4] = o;
        }
    }

    if (t < 256) {
        unsigned int nxt = (t == 255) ? 0u : S2[t + 1];
        if (S2[t] >= TOPN && nxt < TOPN) { gsel = t; above_s = nxt; }
    }
    __syncthreads();
    int gg = gsel;
    unsigned int above = above_s;
    unsigned int fv = 0;
    if (t < 256) fv = g_z.hist[gg * 256 + t];
    __syncthreads();
    if (t < 256) s[t] = fv;
    __syncthreads();
    for (int off = 1; off < 256; off <<= 1) {
        unsigned int v = 0;
        if (t < 256) v = (t + off < 256) ? s[t + off] : 0u;
        __syncthreads();
        if (t < 256) s[t] += v;
        __syncthreads();
    }
    if (t < 256) {
        unsigned int nxt2 = (t == 255) ? 0u : s[t + 1];
        if (above + s[t] >= TOPN && above + nxt2 < TOPN) {
            g_thresh = (unsigned int)(gg * 256 + t);
            g_cand_count = above + s[t];
        }
    }
}

// ---------------- K3: compact candidates into bucket-ordered slots ----------------
__global__ void k_compact() {
    int t = blockIdx.x * blockDim.x + threadIdx.x;
    if (t >= NTOT) return;
    unsigned int srt = g_srt[t];
    unsigned int b = srt >> 16;
    if (b >= g_thresh) {
        int a = t / HW;
        int k = t - a * HW;
        int i_ref = k * NA + a;   // reference flatten order (tiebreak)
        unsigned long long key =
            ((unsigned long long)srt << 32) | (0xFFFFFFFFu - (unsigned int)i_ref);
        unsigned int end = g_sfx[b - 1];                 // b >= thresh >= 1
        unsigned int old = atomicSub(&g_z.hist[b], 1u);  // counts down
        unsigned int slot = end - old;                   // bucket base .. end-1
        if (slot < CAND_MAX) g_cand[slot] = key;
    }
}

// ---------------- K4: in-bucket exact rank + gather + scatter ----------------
__global__ void k_ranksc() {
    unsigned int C = g_cand_count;
    if (C > CAND_MAX) C = CAND_MAX;
    int i = blockIdx.x * blockDim.x + threadIdx.x;
    if (i >= (int)C) return;
    unsigned long long mykey = g_cand[i];
    unsigned int b = (unsigned int)(mykey >> 48);

    unsigned int idx = 0xFFFFFFFFu - (unsigned int)(mykey & 0xFFFFFFFFull);
    int a = idx % NA;
    int k = idx / NA;
    float4 box = g_boxes[a * HW + k];
    unsigned int base = g_sfx[b];
    unsigned int end = g_sfx[b - 1];
    if (end > C) end = C;

    unsigned int rank = base;
    for (unsigned int j = base; j < end; j++)
        rank += (g_cand[j] > mykey) ? 1u : 0u;

    if (rank < TOPN) {
        g_top_boxes[rank] = box;
        bool vkey = ((unsigned int)(mykey >> 32)) > 0x007FFFFFu;
        if (!vkey) atomicOr(&g_z.sup[rank >> 6], 1ull << (rank & 63));
    }
}

// ---------------- K5: early NMS bitmask, ranks < RTOP only ----------------
__global__ void k_maskR() {
    int bi = blockIdx.y, bj = blockIdx.x;
    if (bj < bi) return;
    int t = threadIdx.x;
    int i = bi * 64 + t;                 // < RTOP < TOPN
    __shared__ float4 bb[64];
    __shared__ float ar[64];
    int jg0 = bj * 64 + t;
    float4 b0 = g_top_boxes[jg0];
    bb[t] = b0;
    ar[t] = (b0.z - b0.x) * (b0.w - b0.y);
    __syncthreads();
    float4 bi_box = g_top_boxes[i];
    float area_i = (bi_box.z - bi_box.x) * (bi_box.w - bi_box.y);
    unsigned long long m = 0ull;
#pragma unroll 4
    for (int jj = 0; jj < 64; jj++) {
        int jg = bj * 64 + jj;
        float4 bj_box = bb[jj];
        float ix1 = fmaxf(bi_box.x, bj_box.x);
        float iy1 = fmaxf(bi_box.y, bj_box.y);
        float ix2 = fminf(bi_box.z, bj_box.z);
        float iy2 = fminf(bi_box.w, bj_box.w);
        float inter = fmaxf(ix2 - ix1, 0.f) * fmaxf(iy2 - iy1, 0.f);
        float denom = fmaxf(area_i + ar[jj] - inter, 1e-9f);
        float iou = inter / denom;
        if (iou > 0.7f && jg > i) m |= (1ull << jj);
    }
    g_maskR[i * RW + bj] = m;
}

// ---------------- K6: collect with in-kernel slow-path continuation --------
// Early scan over ranks < RTOP via precomputed mask; if fewer than POSTN kept,
// continue greedy over ranks [RTOP, TOPN): box i is kept iff IoU <= thresh
// against every previously KEPT box (suppression by non-kept boxes is
// irrelevant in greedy NMS). Control flow uniform across the block.
__global__ void __launch_bounds__(CTH) k_collectR(float* __restrict__ out) {
    __shared__ unsigned long long remv[RW];
    __shared__ int klist[POSTN];
    __shared__ float4 kbox[POSTN];                     // kept boxes (slow path)
    __shared__ unsigned long long tiles[2][64 * RW];   // 16 KB
    int tid = threadIdx.x;

    for (int t = tid; t < POSTN * 5; t += CTH) out[t] = 0.f;   // d_out is poisoned
    if (tid < RW) remv[tid] = g_z.sup[tid];
    __syncthreads();

    // prefetch tile 0 (alive rows only)
    {
        unsigned long long rv = remv[0];
        for (int t = tid; t < 64 * (RW / 2); t += CTH) {
            int r = t >> 3, c = t & 7;
            if (!((rv >> r) & 1ull))
                cp_async16(&tiles[0][r * RW + 2 * c], &g_maskR[r * RW + 2 * c]);
        }
        cp_async_commit();
    }
    cp_async_wait0();
    __syncthreads();

    int kept = 0;
    for (int ib = 0; ib < RT; ib++) {
        unsigned long long* tile = tiles[ib & 1];
        int ibe = ib & ~1;
        int off = ib - ibe;
        int wfull = RW - ibe;              // even
        if (ib + 1 < RT) {
            int nb2 = ib + 1;
            int ibe2 = nb2 & ~1;
            int wfull2 = RW - ibe2;        // even
            int half2 = wfull2 >> 1;
            unsigned long long rv = remv[nb2];
            unsigned long long* dst = tiles[nb2 & 1];
            for (int t = tid; t < 64 * half2; t += CTH) {
                int r = t / half2, c = t - r * half2;
                if (!((rv >> r) & 1ull))
                    cp_async16(&dst[r * wfull2 + 2 * c],
                               &g_maskR[(nb2 * 64 + r) * RW + ibe2 + 2 * c]);
            }
        }
        cp_async_commit();

        int wcnt = RW - ib;
        unsigned long long rcur = remv[ib];
        unsigned long long acc = 0ull;
        int w = tid;                       // owns word ib+w (0 < w < wcnt)
        while (true) {
            unsigned long long avail = ~rcur;
            if (avail == 0ull) break;
            int bit = __ffsll((long long)avail) - 1;
            if (tid == 0) klist[kept] = ib * 64 + bit;
            kept++;
            rcur |= tile[bit * wfull + off] | (1ull << bit);
            if (w > 0 && w < wcnt) acc |= tile[bit * wfull + off + w];
            if (kept >= POSTN) break;
        }
        if (w > 0 && w < wcnt) remv[ib + w] |= acc;
        if (kept >= POSTN) break;
        cp_async_wait0();
        __syncthreads();
    }
    cp_async_wait0();
    __syncthreads();

    // ---- rare slow path: continue greedy beyond RTOP against kept set ----
    if (kept < POSTN) {
        for (int t = tid; t < kept; t += CTH) kbox[t] = g_top_boxes[klist[t]];
        __syncthreads();
        for (int i = RTOP; i < TOPN && kept < POSTN; i++) {
            // validity (uniform read)
            if ((g_z.sup[i >> 6] >> (i & 63)) & 1ull) continue;
            float4 bi = g_top_boxes[i];
            float area_i = (bi.z - bi.x) * (bi.w - bi.y);
            int sup = 0;
            for (int j = tid; j < kept; j += CTH) {
                float4 bj = kbox[j];
                float ix1 = fmaxf(bi.x, bj.x);
                float iy1 = fmaxf(bi.y, bj.y);
                float ix2 = fminf(bi.z, bj.z);
                float iy2 = fminf(bi.w, bj.w);
                float inter = fmaxf(ix2 - ix1, 0.f) * fmaxf(iy2 - iy1, 0.f);
                float area_j = (bj.z - bj.x) * (bj.w - bj.y);
                float denom = fmaxf(area_i + area_j - inter, 1e-9f);
                if (inter > 0.7f * denom) sup = 1;
            }
            if (__syncthreads_or(sup) == 0) {
                if (tid == 0) klist[kept] = i;
                kbox[kept] = bi;           // every thread has bi; same value
                kept++;
            }
        }
        __syncthreads();
    }

    for (int t = tid; t < kept; t += CTH) {
        int idx = klist[t];
        float4 b = g_top_boxes[idx];
        float* row = out + t * 5;
        row[0] = 0.f; row[1] = b.x; row[2] = b.y; row[3] = b.z; row[4] = b.w;
    }
}

extern "C" void kernel_launch(void* const* d_in, const int* in_sizes, int n_in,
                              void* d_out, int out_size) {
    const float* scores  = (const float*)d_in[0];
    const float* deltas  = (const float*)d_in[1];
    const float* im_info = (const float*)d_in[2];
    float* out = (float*)d_out;

    void* p;
    cudaGetSymbolAddress(&p, g_z);
    cudaMemsetAsync(p, 0, sizeof(ZeroBlock));

    k_score_box<<<(NTOT + 255) / 256, 256>>>(scores, deltas, im_info);
    k_thresh<<<1, 1024>>>();
    k_compact<<<(NTOT + 255) / 256, 256>>>();
    k_ranksc<<<CAND_MAX / 128, 128>>>();

    dim3 gmr(RT, RT);
    k_maskR<<<gmr, 64>>>();
    k_collectR<<<1, CTH>>>(out);
}